// round 7
// baseline (speedup 1.0000x reference)
#include <cuda_runtime.h>
#include <mma.h>
using namespace nvcuda;

#define NN  50000
#define NNP 50048          // 391 * 128, padded row count for unguarded GEMM stores
#define NE  800000
#define HID 256
#define OC  40
#define SB  49             // scan blocks: 49*1024 >= NN

// ---------------- scratch (static device allocations) ---------------------------
__device__ float g_deg[NN];
__device__ float g_dinv[NN];
__device__ int   g_cnt[NN];
__device__ int   g_off[NN + 1];
__device__ int   g_cur[NN];
__device__ int   g_bsum[SB];
__device__ int   g_ccol[NE];
__device__ float g_cw[NE];
__device__ float g_bufA[NNP * HID];
__device__ float g_bufB[NNP * HID];
__device__ float g_t40[NN * OC];
__device__ float g_y0[NN * OC];
__device__ float g_y1[NN * OC];
__device__ float g_y2[NN * OC];
__device__ float g_y3[NN * OC];
__device__ float g_bnsum[HID];
__device__ float g_bnsq[HID];
__device__ float g_scale[HID];
__device__ float g_shift[HID];

// ---------------- normalization + CSR build --------------------------------------
__global__ void k_fillinit(float* degp, int* cntp, int n) {
    int i = blockIdx.x * blockDim.x + threadIdx.x;
    if (i < n) { degp[i] = 1.0f; cntp[i] = 0; }
}

__global__ void k_degcnt(const int* __restrict__ row, const float* __restrict__ w) {
    int e = blockIdx.x * blockDim.x + threadIdx.x;
    if (e < NE) {
        int r = row[e];
        atomicAdd(&g_deg[r], w[e]);
        atomicAdd(&g_cnt[r], 1);
    }
}

__global__ void k_dinv() {
    int i = blockIdx.x * blockDim.x + threadIdx.x;
    if (i < NN) {
        float d = g_deg[i];
        g_dinv[i] = (d > 0.f) ? rsqrtf(fmaxf(d, 1e-12f)) : 0.f;
    }
}

// phase 1: per-block exclusive scan (local), block totals to g_bsum
__global__ void k_scan1() {
    __shared__ int wsum[32];
    int tid = threadIdx.x, lane = tid & 31, wid = tid >> 5;
    int i = blockIdx.x * 1024 + tid;
    int v = (i < NN) ? g_cnt[i] : 0;
    int x = v;
    #pragma unroll
    for (int o = 1; o < 32; o <<= 1) {
        int t = __shfl_up_sync(0xFFFFFFFFu, x, o);
        if (lane >= o) x += t;
    }
    if (lane == 31) wsum[wid] = x;
    __syncthreads();
    if (wid == 0) {
        int s = wsum[lane];
        #pragma unroll
        for (int o = 1; o < 32; o <<= 1) {
            int t = __shfl_up_sync(0xFFFFFFFFu, s, o);
            if (lane >= o) s += t;
        }
        wsum[lane] = s;
    }
    __syncthreads();
    int warpoff = (wid > 0) ? wsum[wid - 1] : 0;
    if (i < NN) g_off[i] = warpoff + x - v;           // local exclusive
    if (tid == 1023) g_bsum[blockIdx.x] = warpoff + x; // block total
}

// phase 2: serial scan of SB block sums (tiny)
__global__ void k_scan2() {
    int acc = 0;
    for (int b = 0; b < SB; b++) {
        int t = g_bsum[b];
        g_bsum[b] = acc;
        acc += t;
    }
    g_off[NN] = acc;
}

// phase 3: add block offsets, copy to g_cur
__global__ void k_scan3() {
    int i = blockIdx.x * 1024 + threadIdx.x;
    if (i < NN) {
        int v = g_off[i] + g_bsum[blockIdx.x];
        g_off[i] = v;
        g_cur[i] = v;
    }
}

__global__ void k_scatter(const int* __restrict__ row, const int* __restrict__ col,
                          const float* __restrict__ w) {
    int e = blockIdx.x * blockDim.x + threadIdx.x;
    if (e < NE) {
        int r = row[e], c = col[e];
        int p = atomicAdd(&g_cur[r], 1);
        g_ccol[p] = c;
        g_cw[p] = g_dinv[r] * w[e] * g_dinv[c];
    }
}

// ---------------- TF32 tensor-core GEMM: C[M,N] = op(A)[M,K] @ B[K,N] ------------
// block tile 128x128, 8 warps (2 m x 4 n), warp tile 64x32, k chunk 16.
// bn != 0: A element (channel = k index) transformed relu(a*scale[k]+shift[k]).
__global__ void __launch_bounds__(256) k_gemm_tf32(const float* __restrict__ A,
                                                   const float* __restrict__ B,
                                                   float* __restrict__ C,
                                                   int M, int N, int K, int bn) {
    __shared__ float As[128][24];    // [m][k], k chunk 16, pad 24
    __shared__ float Bs[16][136];    // [k][n], n chunk 128, pad 136
    int bm = blockIdx.x * 128, bnn = blockIdx.y * 128;
    int tid = threadIdx.x;
    int warp = tid >> 5;
    int wm = (warp >> 2) * 64;       // 2 warps along m
    int wn = (warp & 3) * 32;        // 4 warps along n

    wmma::fragment<wmma::accumulator, 16, 16, 8, float> c[4][2];
    #pragma unroll
    for (int i = 0; i < 4; i++)
        #pragma unroll
        for (int j = 0; j < 2; j++)
            wmma::fill_fragment(c[i][j], 0.f);

    for (int k0 = 0; k0 < K; k0 += 16) {
        // A tile 128x16: thread -> m = tid>>1, 8 consecutive k (two float4)
        {
            int m  = tid >> 1;
            int ks = (tid & 1) * 8;
            int gr = bm + m;
            if (gr < M) {
                const float4* p = (const float4*)&A[(long long)gr * K + k0 + ks];
                #pragma unroll
                for (int i = 0; i < 2; i++) {
                    float4 v = p[i];
                    if (bn) {
                        int cc = k0 + ks + i * 4;
                        v.x = fmaxf(v.x * g_scale[cc + 0] + g_shift[cc + 0], 0.f);
                        v.y = fmaxf(v.y * g_scale[cc + 1] + g_shift[cc + 1], 0.f);
                        v.z = fmaxf(v.z * g_scale[cc + 2] + g_shift[cc + 2], 0.f);
                        v.w = fmaxf(v.w * g_scale[cc + 3] + g_shift[cc + 3], 0.f);
                    }
                    As[m][ks + i * 4 + 0] = wmma::__float_to_tf32(v.x);
                    As[m][ks + i * 4 + 1] = wmma::__float_to_tf32(v.y);
                    As[m][ks + i * 4 + 2] = wmma::__float_to_tf32(v.z);
                    As[m][ks + i * 4 + 3] = wmma::__float_to_tf32(v.w);
                }
            } else {
                #pragma unroll
                for (int i = 0; i < 8; i++) As[m][ks + i] = 0.f;
            }
        }
        // B tile 16x128: thread -> k = tid>>4, 8 consecutive n (two float4)
        {
            int k  = tid >> 4;
            int n8 = (tid & 15) * 8;
            const float4* p = (const float4*)&B[(long long)(k0 + k) * N + bnn + n8];
            #pragma unroll
            for (int i = 0; i < 2; i++) {
                float4 v = p[i];
                Bs[k][n8 + i * 4 + 0] = wmma::__float_to_tf32(v.x);
                Bs[k][n8 + i * 4 + 1] = wmma::__float_to_tf32(v.y);
                Bs[k][n8 + i * 4 + 2] = wmma::__float_to_tf32(v.z);
                Bs[k][n8 + i * 4 + 3] = wmma::__float_to_tf32(v.w);
            }
        }
        __syncthreads();
        #pragma unroll
        for (int kk = 0; kk < 16; kk += 8) {
            wmma::fragment<wmma::matrix_a, 16, 16, 8, wmma::precision::tf32, wmma::row_major> a[4];
            wmma::fragment<wmma::matrix_b, 16, 16, 8, wmma::precision::tf32, wmma::row_major> b[2];
            #pragma unroll
            for (int i = 0; i < 4; i++)
                wmma::load_matrix_sync(a[i], &As[wm + 16 * i][kk], 24);
            #pragma unroll
            for (int j = 0; j < 2; j++)
                wmma::load_matrix_sync(b[j], &Bs[kk][wn + 16 * j], 136);
            #pragma unroll
            for (int i = 0; i < 4; i++)
                #pragma unroll
                for (int j = 0; j < 2; j++)
                    wmma::mma_sync(c[i][j], a[i], b[j], c[i][j]);
        }
        __syncthreads();
    }
    #pragma unroll
    for (int i = 0; i < 4; i++)
        #pragma unroll
        for (int j = 0; j < 2; j++)
            wmma::store_matrix_sync(
                &C[(long long)(bm + wm + 16 * i) * N + bnn + wn + 16 * j],
                c[i][j], N, wmma::mem_row_major);
}

// ---------------- GEMM: C[M,40] = relu(bn(A))[M,K] @ B[K,40] (SIMT) --------------
__global__ void k_gemm40(const float* __restrict__ A, const float* __restrict__ B,
                         float* __restrict__ C, int M, int K) {
    __shared__ float As[64][33];
    __shared__ float Bs[32][40];
    int bm = blockIdx.x * 64;
    int r  = threadIdx.x >> 2;
    int cg = threadIdx.x & 3;
    float acc[10] = {};
    for (int k0 = 0; k0 < K; k0 += 32) {
        int kk = (threadIdx.x & 3) * 8;
        int gr = bm + r;
        #pragma unroll
        for (int i = 0; i < 8; i++) {
            int c = k0 + kk + i;
            float v = (gr < M) ? A[(long long)gr * K + c] : 0.f;
            As[r][kk + i] = fmaxf(v * g_scale[c] + g_shift[c], 0.f);
        }
        for (int i = threadIdx.x; i < 32 * 40; i += 256) {
            int k = i / 40, n = i % 40;
            Bs[k][n] = B[(k0 + k) * 40 + n];
        }
        __syncthreads();
        #pragma unroll
        for (int k = 0; k < 32; k++) {
            float a = As[r][k];
            #pragma unroll
            for (int j = 0; j < 10; j++) acc[j] += a * Bs[k][cg + j * 4];
        }
        __syncthreads();
    }
    int gr = bm + r;
    if (gr < M)
        #pragma unroll
        for (int j = 0; j < 10; j++) C[gr * 40 + cg + j * 4] = acc[j];
}

// ---------------- gather SpMM 256ch: out[r] = d^2*in[r] + bias + sum w*in[col] ---
__global__ void __launch_bounds__(256) k_gspmm256(const float* __restrict__ in,
                                                  float* __restrict__ out,
                                                  const float* __restrict__ bias) {
    __shared__ int   scol[256];
    __shared__ float sw[256];
    int r = blockIdx.x;
    int ch = threadIdx.x;
    int beg = g_off[r], end = g_off[r + 1];
    float d = g_dinv[r];
    float acc = d * d * in[r * HID + ch] + bias[ch];
    for (int j0 = beg; j0 < end; j0 += 256) {
        int m = min(256, end - j0);
        if (ch < m) { scol[ch] = g_ccol[j0 + ch]; sw[ch] = g_cw[j0 + ch]; }
        __syncthreads();
        #pragma unroll 4
        for (int j = 0; j < m; j++)
            acc += sw[j] * in[scol[j] * HID + ch];
        __syncthreads();
    }
    out[r * HID + ch] = acc;
}

// ---------------- 40-channel gather SpMM: triple (features + 2 label chains) -----
__global__ void __launch_bounds__(256) k_gspmm40t(
    const float* __restrict__ in0, float* __restrict__ out0, const float* __restrict__ bias0,
    const float* __restrict__ in1, float* __restrict__ out1,
    const float* __restrict__ in2, float* __restrict__ out2) {
    int r = blockIdx.x * 8 + (threadIdx.x >> 5);
    if (r >= NN) return;
    int lane = threadIdx.x & 31;
    int beg = g_off[r], end = g_off[r + 1];
    float d = g_dinv[r];
    float dd = d * d;
    int rb = r * OC + lane;
    float a0 = dd * in0[rb], a1 = dd * in1[rb], a2 = dd * in2[rb];
    float b0 = 0.f, b1 = 0.f, b2 = 0.f;
    if (lane < 8) {
        b0 = dd * in0[rb + 32]; b1 = dd * in1[rb + 32]; b2 = dd * in2[rb + 32];
    }
    #pragma unroll 2
    for (int j = beg; j < end; j++) {
        int cb = g_ccol[j] * OC + lane;
        float w = g_cw[j];
        a0 += w * in0[cb]; a1 += w * in1[cb]; a2 += w * in2[cb];
        if (lane < 8) {
            b0 += w * in0[cb + 32]; b1 += w * in1[cb + 32]; b2 += w * in2[cb + 32];
        }
    }
    a0 += bias0[lane];
    out0[rb] = a0; out1[rb] = a1; out2[rb] = a2;
    if (lane < 8) {
        b0 += bias0[32 + lane];
        out0[rb + 32] = b0; out1[rb + 32] = b1; out2[rb + 32] = b2;
    }
}

// dual version (two label chains, no bias)
__global__ void __launch_bounds__(256) k_gspmm40d(
    const float* __restrict__ in1, float* __restrict__ out1,
    const float* __restrict__ in2, float* __restrict__ out2) {
    int r = blockIdx.x * 8 + (threadIdx.x >> 5);
    if (r >= NN) return;
    int lane = threadIdx.x & 31;
    int beg = g_off[r], end = g_off[r + 1];
    float d = g_dinv[r];
    float dd = d * d;
    int rb = r * OC + lane;
    float a1 = dd * in1[rb], a2 = dd * in2[rb];
    float b1 = 0.f, b2 = 0.f;
    if (lane < 8) { b1 = dd * in1[rb + 32]; b2 = dd * in2[rb + 32]; }
    #pragma unroll 2
    for (int j = beg; j < end; j++) {
        int cb = g_ccol[j] * OC + lane;
        float w = g_cw[j];
        a1 += w * in1[cb]; a2 += w * in2[cb];
        if (lane < 8) { b1 += w * in1[cb + 32]; b2 += w * in2[cb + 32]; }
    }
    out1[rb] = a1; out2[rb] = a2;
    if (lane < 8) { out1[rb + 32] = b1; out2[rb + 32] = b2; }
}

// ---------------- BatchNorm stats -------------------------------------------------
__global__ void k_bnzero() {
    int c = threadIdx.x;
    g_bnsum[c] = 0.f;
    g_bnsq[c]  = 0.f;
}

__global__ void k_bnstats(const float* __restrict__ h) {
    int c = threadIdx.x;
    float s = 0.f, s2 = 0.f;
    for (int r = blockIdx.x; r < NN; r += gridDim.x) {
        float v = h[r * HID + c];
        s += v;
        s2 += v * v;
    }
    atomicAdd(&g_bnsum[c], s);
    atomicAdd(&g_bnsq[c], s2);
}

__global__ void k_bnfin(const float* __restrict__ gamma, const float* __restrict__ beta) {
    int c = threadIdx.x;
    float mu  = g_bnsum[c] * (1.f / NN);
    float var = g_bnsq[c] * (1.f / NN) - mu * mu;
    float sc  = gamma[c] * rsqrtf(var + 1e-5f);
    g_scale[c] = sc;
    g_shift[c] = beta[c] - mu * sc;
}

// ---------------- host orchestration ----------------------------------------------
extern "C" void kernel_launch(void* const* d_in, const int* in_sizes, int n_in,
                              void* d_out, int out_size) {
    const float* x    = (const float*)d_in[0];
    const int*   ei   = (const int*)d_in[1];
    const int*   row  = ei;
    const int*   col  = ei + NE;
    const float* lab0 = (const float*)d_in[2];
    const float* lab1 = (const float*)d_in[3];
    const float* ew   = (const float*)d_in[4];
    const float* W0   = (const float*)d_in[5];
    const float* b0   = (const float*)d_in[6];
    const float* W1   = (const float*)d_in[7];
    const float* b1   = (const float*)d_in[8];
    const float* W2   = (const float*)d_in[9];
    const float* b2   = (const float*)d_in[10];
    const float* g0   = (const float*)d_in[11];
    const float* be0  = (const float*)d_in[12];
    const float* g1   = (const float*)d_in[13];
    const float* be1  = (const float*)d_in[14];
    float* out = (float*)d_out;

    float *bufA, *bufB, *t40, *y0, *y1, *y2, *y3, *degp;
    int* cntp;
    cudaGetSymbolAddress((void**)&bufA, g_bufA);
    cudaGetSymbolAddress((void**)&bufB, g_bufB);
    cudaGetSymbolAddress((void**)&t40,  g_t40);
    cudaGetSymbolAddress((void**)&y0,   g_y0);
    cudaGetSymbolAddress((void**)&y1,   g_y1);
    cudaGetSymbolAddress((void**)&y2,   g_y2);
    cudaGetSymbolAddress((void**)&y3,   g_y3);
    cudaGetSymbolAddress((void**)&degp, g_deg);
    cudaGetSymbolAddress((void**)&cntp, g_cnt);

    const int T = 256;
    const int gN   = (NN + T - 1) / T;
    const int gE   = (NE + T - 1) / T;
    const int gM64 = (NN + 63) / 64;
    const int gRW  = (NN + 7) / 8;

    // normalization + CSR build (multi-block scan)
    k_fillinit<<<gN, T>>>(degp, cntp, NN);
    k_degcnt<<<gE, T>>>(row, ew);
    k_dinv<<<gN, T>>>();
    k_scan1<<<SB, 1024>>>();
    k_scan2<<<1, 1>>>();
    k_scan3<<<SB, 1024>>>();
    k_scatter<<<gE, T>>>(row, col, ew);

    // ---- layer 0: gemm -> spmm -> BN stats (apply fused into next gemm)
    dim3 gg(NNP / 128, HID / 128);
    k_gemm_tf32<<<gg, T>>>(x, W0, bufA, NN, HID, 512, 0);
    k_gspmm256<<<NN, HID>>>(bufA, bufB, b0);
    k_bnzero<<<1, HID>>>();
    k_bnstats<<<512, HID>>>(bufB);
    k_bnfin<<<1, HID>>>(g0, be0);

    // ---- layer 1: gemm (BN0+ReLU fused in A-load) -> spmm -> BN stats
    k_gemm_tf32<<<gg, T>>>(bufB, W1, bufA, NN, HID, 256, 1);
    k_gspmm256<<<NN, HID>>>(bufA, bufB, b1);
    k_bnzero<<<1, HID>>>();
    k_bnstats<<<512, HID>>>(bufB);
    k_bnfin<<<1, HID>>>(g1, be1);

    // ---- layer 2 GEMM (BN1+ReLU fused in A-load) into t40
    k_gemm40<<<gM64, T>>>(bufB, W2, t40, NN, HID);

    // ---- fused 40-channel SpMMs
    float* dst1 = out + NN * OC;
    float* dst2 = out + 2 * NN * OC;
    k_gspmm40t<<<gRW, T>>>(t40, out, b2, lab0, y0, lab1, y2);
    k_gspmm40d<<<gRW, T>>>(y0, y1, y2, y3);
    k_gspmm40d<<<gRW, T>>>(y1, dst1, y3, dst2);
}

// round 8
// speedup vs baseline: 1.4811x; 1.4811x over previous
#include <cuda_runtime.h>
#include <mma.h>
using namespace nvcuda;

#define NN  50000
#define NNP 50048          // 391 * 128, padded row count for unguarded GEMM stores
#define NE  800000
#define HID 256
#define OC  40
#define SB  49             // scan blocks: 49*1024 >= NN

// ---------------- scratch (static device allocations) ---------------------------
__device__ float g_deg[NN];
__device__ float g_dinv[NN];
__device__ int   g_cnt[NN];
__device__ int   g_off[NN + 1];
__device__ int   g_cur[NN];
__device__ int   g_bsum[SB];
__device__ int   g_ccol[NE];
__device__ float g_cw[NE];
__device__ float g_bufA[NNP * HID];
__device__ float g_bufB[NNP * HID];
__device__ float g_t40[NN * OC];
__device__ float g_y0[NN * OC];
__device__ float g_y1[NN * OC];
__device__ float g_y2[NN * OC];
__device__ float g_y3[NN * OC];
__device__ float g_bnsum[HID];
__device__ float g_bnsq[HID];
__device__ float g_scale[HID];
__device__ float g_shift[HID];

// ---------------- normalization + CSR build --------------------------------------
__global__ void k_fillinit(float* degp, int* cntp, int n) {
    int i = blockIdx.x * blockDim.x + threadIdx.x;
    if (i < n) { degp[i] = 1.0f; cntp[i] = 0; }
}

__global__ void k_degcnt(const int* __restrict__ row, const float* __restrict__ w) {
    int e = blockIdx.x * blockDim.x + threadIdx.x;
    if (e < NE) {
        int r = row[e];
        atomicAdd(&g_deg[r], w[e]);
        atomicAdd(&g_cnt[r], 1);
    }
}

__global__ void k_dinv() {
    int i = blockIdx.x * blockDim.x + threadIdx.x;
    if (i < NN) {
        float d = g_deg[i];
        g_dinv[i] = (d > 0.f) ? rsqrtf(fmaxf(d, 1e-12f)) : 0.f;
    }
}

// phase 1: per-block exclusive scan (local), block totals to g_bsum
__global__ void k_scan1() {
    __shared__ int wsum[32];
    int tid = threadIdx.x, lane = tid & 31, wid = tid >> 5;
    int i = blockIdx.x * 1024 + tid;
    int v = (i < NN) ? g_cnt[i] : 0;
    int x = v;
    #pragma unroll
    for (int o = 1; o < 32; o <<= 1) {
        int t = __shfl_up_sync(0xFFFFFFFFu, x, o);
        if (lane >= o) x += t;
    }
    if (lane == 31) wsum[wid] = x;
    __syncthreads();
    if (wid == 0) {
        int s = wsum[lane];
        #pragma unroll
        for (int o = 1; o < 32; o <<= 1) {
            int t = __shfl_up_sync(0xFFFFFFFFu, s, o);
            if (lane >= o) s += t;
        }
        wsum[lane] = s;
    }
    __syncthreads();
    int warpoff = (wid > 0) ? wsum[wid - 1] : 0;
    if (i < NN) g_off[i] = warpoff + x - v;            // local exclusive
    if (tid == 1023) g_bsum[blockIdx.x] = warpoff + x;  // block total
}

// phase 2: serial scan of SB block sums (tiny)
__global__ void k_scan2() {
    int acc = 0;
    for (int b = 0; b < SB; b++) {
        int t = g_bsum[b];
        g_bsum[b] = acc;
        acc += t;
    }
    g_off[NN] = acc;
}

// phase 3: add block offsets, copy to g_cur
__global__ void k_scan3() {
    int i = blockIdx.x * 1024 + threadIdx.x;
    if (i < NN) {
        int v = g_off[i] + g_bsum[blockIdx.x];
        g_off[i] = v;
        g_cur[i] = v;
    }
}

__global__ void k_scatter(const int* __restrict__ row, const int* __restrict__ col,
                          const float* __restrict__ w) {
    int e = blockIdx.x * blockDim.x + threadIdx.x;
    if (e < NE) {
        int r = row[e], c = col[e];
        int p = atomicAdd(&g_cur[r], 1);
        g_ccol[p] = c;
        g_cw[p] = g_dinv[r] * w[e] * g_dinv[c];
    }
}

// ---------------- TF32 tensor-core GEMM: C[M,N] = op(A)[M,K] @ B[K,N] ------------
// ROUND-6 CONFIG (measured good): block tile 128x64, 8 warps (4 m x 2 n),
// warp tile 32x32, k chunk 32, smem pads 40/72.
// bn != 0: A element (channel = k index) transformed relu(a*scale[k]+shift[k]).
__global__ void __launch_bounds__(256) k_gemm_tf32(const float* __restrict__ A,
                                                   const float* __restrict__ B,
                                                   float* __restrict__ C,
                                                   int M, int N, int K, int bn) {
    __shared__ float As[128][40];   // [m][k], k chunk 32
    __shared__ float Bs[32][72];    // [k][n], n chunk 64
    int bm = blockIdx.x * 128, bnn = blockIdx.y * 64;
    int tid = threadIdx.x;
    int warp = tid >> 5;
    int wm = (warp >> 1) * 32;
    int wn = (warp & 1) * 32;

    wmma::fragment<wmma::accumulator, 16, 16, 8, float> c00, c01, c10, c11;
    wmma::fill_fragment(c00, 0.f); wmma::fill_fragment(c01, 0.f);
    wmma::fill_fragment(c10, 0.f); wmma::fill_fragment(c11, 0.f);

    for (int k0 = 0; k0 < K; k0 += 32) {
        {
            int m  = tid >> 1;
            int ks = (tid & 1) * 16;
            int gr = bm + m;
            if (gr < M) {
                const float4* p = (const float4*)&A[(long long)gr * K + k0 + ks];
                #pragma unroll
                for (int i = 0; i < 4; i++) {
                    float4 v = p[i];
                    if (bn) {
                        int cc = k0 + ks + i * 4;
                        v.x = fmaxf(v.x * g_scale[cc + 0] + g_shift[cc + 0], 0.f);
                        v.y = fmaxf(v.y * g_scale[cc + 1] + g_shift[cc + 1], 0.f);
                        v.z = fmaxf(v.z * g_scale[cc + 2] + g_shift[cc + 2], 0.f);
                        v.w = fmaxf(v.w * g_scale[cc + 3] + g_shift[cc + 3], 0.f);
                    }
                    As[m][ks + i * 4 + 0] = wmma::__float_to_tf32(v.x);
                    As[m][ks + i * 4 + 1] = wmma::__float_to_tf32(v.y);
                    As[m][ks + i * 4 + 2] = wmma::__float_to_tf32(v.z);
                    As[m][ks + i * 4 + 3] = wmma::__float_to_tf32(v.w);
                }
            } else {
                #pragma unroll
                for (int i = 0; i < 16; i++) As[m][ks + i] = 0.f;
            }
        }
        {
            int k  = tid >> 3;
            int n8 = (tid & 7) * 8;
            const float4* p = (const float4*)&B[(long long)(k0 + k) * N + bnn + n8];
            #pragma unroll
            for (int i = 0; i < 2; i++) {
                float4 v = p[i];
                Bs[k][n8 + i * 4 + 0] = wmma::__float_to_tf32(v.x);
                Bs[k][n8 + i * 4 + 1] = wmma::__float_to_tf32(v.y);
                Bs[k][n8 + i * 4 + 2] = wmma::__float_to_tf32(v.z);
                Bs[k][n8 + i * 4 + 3] = wmma::__float_to_tf32(v.w);
            }
        }
        __syncthreads();
        #pragma unroll
        for (int kk = 0; kk < 32; kk += 8) {
            wmma::fragment<wmma::matrix_a, 16, 16, 8, wmma::precision::tf32, wmma::row_major> a0, a1;
            wmma::fragment<wmma::matrix_b, 16, 16, 8, wmma::precision::tf32, wmma::row_major> b0, b1;
            wmma::load_matrix_sync(a0, &As[wm +  0][kk], 40);
            wmma::load_matrix_sync(a1, &As[wm + 16][kk], 40);
            wmma::load_matrix_sync(b0, &Bs[kk][wn +  0], 72);
            wmma::load_matrix_sync(b1, &Bs[kk][wn + 16], 72);
            wmma::mma_sync(c00, a0, b0, c00);
            wmma::mma_sync(c01, a0, b1, c01);
            wmma::mma_sync(c10, a1, b0, c10);
            wmma::mma_sync(c11, a1, b1, c11);
        }
        __syncthreads();
    }
    float* cp = &C[(long long)(bm + wm) * N + bnn + wn];
    wmma::store_matrix_sync(cp,               c00, N, wmma::mem_row_major);
    wmma::store_matrix_sync(cp + 16,          c01, N, wmma::mem_row_major);
    wmma::store_matrix_sync(cp + 16 * N,      c10, N, wmma::mem_row_major);
    wmma::store_matrix_sync(cp + 16 * N + 16, c11, N, wmma::mem_row_major);
}

// ---------------- GEMM: C[M,40] = relu(bn(A))[M,K] @ B[K,40] (SIMT) --------------
__global__ void k_gemm40(const float* __restrict__ A, const float* __restrict__ B,
                         float* __restrict__ C, int M, int K) {
    __shared__ float As[64][33];
    __shared__ float Bs[32][40];
    int bm = blockIdx.x * 64;
    int r  = threadIdx.x >> 2;
    int cg = threadIdx.x & 3;
    float acc[10] = {};
    for (int k0 = 0; k0 < K; k0 += 32) {
        int kk = (threadIdx.x & 3) * 8;
        int gr = bm + r;
        #pragma unroll
        for (int i = 0; i < 8; i++) {
            int c = k0 + kk + i;
            float v = (gr < M) ? A[(long long)gr * K + c] : 0.f;
            As[r][kk + i] = fmaxf(v * g_scale[c] + g_shift[c], 0.f);
        }
        for (int i = threadIdx.x; i < 32 * 40; i += 256) {
            int k = i / 40, n = i % 40;
            Bs[k][n] = B[(k0 + k) * 40 + n];
        }
        __syncthreads();
        #pragma unroll
        for (int k = 0; k < 32; k++) {
            float a = As[r][k];
            #pragma unroll
            for (int j = 0; j < 10; j++) acc[j] += a * Bs[k][cg + j * 4];
        }
        __syncthreads();
    }
    int gr = bm + r;
    if (gr < M)
        #pragma unroll
        for (int j = 0; j < 10; j++) C[gr * 40 + cg + j * 4] = acc[j];
}

// ---------------- gather SpMM 256ch: out[r] = d^2*in[r] + bias + sum w*in[col] ---
__global__ void __launch_bounds__(256) k_gspmm256(const float* __restrict__ in,
                                                  float* __restrict__ out,
                                                  const float* __restrict__ bias) {
    __shared__ int   scol[256];
    __shared__ float sw[256];
    int r = blockIdx.x;
    int ch = threadIdx.x;
    int beg = g_off[r], end = g_off[r + 1];
    float d = g_dinv[r];
    float acc = d * d * in[r * HID + ch] + bias[ch];
    for (int j0 = beg; j0 < end; j0 += 256) {
        int m = min(256, end - j0);
        if (ch < m) { scol[ch] = g_ccol[j0 + ch]; sw[ch] = g_cw[j0 + ch]; }
        __syncthreads();
        #pragma unroll 4
        for (int j = 0; j < m; j++)
            acc += sw[j] * in[scol[j] * HID + ch];
        __syncthreads();
    }
    out[r * HID + ch] = acc;
}

// ---------------- 40-channel gather SpMM: triple (features + 2 label chains) -----
__global__ void __launch_bounds__(256) k_gspmm40t(
    const float* __restrict__ in0, float* __restrict__ out0, const float* __restrict__ bias0,
    const float* __restrict__ in1, float* __restrict__ out1,
    const float* __restrict__ in2, float* __restrict__ out2) {
    int r = blockIdx.x * 8 + (threadIdx.x >> 5);
    if (r >= NN) return;
    int lane = threadIdx.x & 31;
    int beg = g_off[r], end = g_off[r + 1];
    float d = g_dinv[r];
    float dd = d * d;
    int rb = r * OC + lane;
    float a0 = dd * in0[rb], a1 = dd * in1[rb], a2 = dd * in2[rb];
    float b0 = 0.f, b1 = 0.f, b2 = 0.f;
    if (lane < 8) {
        b0 = dd * in0[rb + 32]; b1 = dd * in1[rb + 32]; b2 = dd * in2[rb + 32];
    }
    #pragma unroll 2
    for (int j = beg; j < end; j++) {
        int cb = g_ccol[j] * OC + lane;
        float w = g_cw[j];
        a0 += w * in0[cb]; a1 += w * in1[cb]; a2 += w * in2[cb];
        if (lane < 8) {
            b0 += w * in0[cb + 32]; b1 += w * in1[cb + 32]; b2 += w * in2[cb + 32];
        }
    }
    a0 += bias0[lane];
    out0[rb] = a0; out1[rb] = a1; out2[rb] = a2;
    if (lane < 8) {
        b0 += bias0[32 + lane];
        out0[rb + 32] = b0; out1[rb + 32] = b1; out2[rb + 32] = b2;
    }
}

// dual version (two label chains, no bias)
__global__ void __launch_bounds__(256) k_gspmm40d(
    const float* __restrict__ in1, float* __restrict__ out1,
    const float* __restrict__ in2, float* __restrict__ out2) {
    int r = blockIdx.x * 8 + (threadIdx.x >> 5);
    if (r >= NN) return;
    int lane = threadIdx.x & 31;
    int beg = g_off[r], end = g_off[r + 1];
    float d = g_dinv[r];
    float dd = d * d;
    int rb = r * OC + lane;
    float a1 = dd * in1[rb], a2 = dd * in2[rb];
    float b1 = 0.f, b2 = 0.f;
    if (lane < 8) { b1 = dd * in1[rb + 32]; b2 = dd * in2[rb + 32]; }
    #pragma unroll 2
    for (int j = beg; j < end; j++) {
        int cb = g_ccol[j] * OC + lane;
        float w = g_cw[j];
        a1 += w * in1[cb]; a2 += w * in2[cb];
        if (lane < 8) { b1 += w * in1[cb + 32]; b2 += w * in2[cb + 32]; }
    }
    out1[rb] = a1; out2[rb] = a2;
    if (lane < 8) { out1[rb + 32] = b1; out2[rb + 32] = b2; }
}

// ---------------- BatchNorm stats -------------------------------------------------
__global__ void k_bnzero() {
    int c = threadIdx.x;
    g_bnsum[c] = 0.f;
    g_bnsq[c]  = 0.f;
}

__global__ void k_bnstats(const float* __restrict__ h) {
    int c = threadIdx.x;
    float s = 0.f, s2 = 0.f;
    for (int r = blockIdx.x; r < NN; r += gridDim.x) {
        float v = h[r * HID + c];
        s += v;
        s2 += v * v;
    }
    atomicAdd(&g_bnsum[c], s);
    atomicAdd(&g_bnsq[c], s2);
}

__global__ void k_bnfin(const float* __restrict__ gamma, const float* __restrict__ beta) {
    int c = threadIdx.x;
    float mu  = g_bnsum[c] * (1.f / NN);
    float var = g_bnsq[c] * (1.f / NN) - mu * mu;
    float sc  = gamma[c] * rsqrtf(var + 1e-5f);
    g_scale[c] = sc;
    g_shift[c] = beta[c] - mu * sc;
}

// ---------------- host orchestration ----------------------------------------------
extern "C" void kernel_launch(void* const* d_in, const int* in_sizes, int n_in,
                              void* d_out, int out_size) {
    const float* x    = (const float*)d_in[0];
    const int*   ei   = (const int*)d_in[1];
    const int*   row  = ei;
    const int*   col  = ei + NE;
    const float* lab0 = (const float*)d_in[2];
    const float* lab1 = (const float*)d_in[3];
    const float* ew   = (const float*)d_in[4];
    const float* W0   = (const float*)d_in[5];
    const float* b0   = (const float*)d_in[6];
    const float* W1   = (const float*)d_in[7];
    const float* b1   = (const float*)d_in[8];
    const float* W2   = (const float*)d_in[9];
    const float* b2   = (const float*)d_in[10];
    const float* g0   = (const float*)d_in[11];
    const float* be0  = (const float*)d_in[12];
    const float* g1   = (const float*)d_in[13];
    const float* be1  = (const float*)d_in[14];
    float* out = (float*)d_out;

    float *bufA, *bufB, *t40, *y0, *y1, *y2, *y3, *degp;
    int* cntp;
    cudaGetSymbolAddress((void**)&bufA, g_bufA);
    cudaGetSymbolAddress((void**)&bufB, g_bufB);
    cudaGetSymbolAddress((void**)&t40,  g_t40);
    cudaGetSymbolAddress((void**)&y0,   g_y0);
    cudaGetSymbolAddress((void**)&y1,   g_y1);
    cudaGetSymbolAddress((void**)&y2,   g_y2);
    cudaGetSymbolAddress((void**)&y3,   g_y3);
    cudaGetSymbolAddress((void**)&degp, g_deg);
    cudaGetSymbolAddress((void**)&cntp, g_cnt);

    const int T = 256;
    const int gN   = (NN + T - 1) / T;
    const int gE   = (NE + T - 1) / T;
    const int gM64 = (NN + 63) / 64;
    const int gRW  = (NN + 7) / 8;

    // normalization + CSR build (multi-block scan)
    k_fillinit<<<gN, T>>>(degp, cntp, NN);
    k_degcnt<<<gE, T>>>(row, ew);
    k_dinv<<<gN, T>>>();
    k_scan1<<<SB, 1024>>>();
    k_scan2<<<1, 1>>>();
    k_scan3<<<SB, 1024>>>();
    k_scatter<<<gE, T>>>(row, col, ew);

    // ---- layer 0: gemm -> spmm -> BN stats (apply fused into next gemm)
    dim3 gg(NNP / 128, HID / 64);
    k_gemm_tf32<<<gg, T>>>(x, W0, bufA, NN, HID, 512, 0);
    k_gspmm256<<<NN, HID>>>(bufA, bufB, b0);
    k_bnzero<<<1, HID>>>();
    k_bnstats<<<512, HID>>>(bufB);
    k_bnfin<<<1, HID>>>(g0, be0);

    // ---- layer 1: gemm (BN0+ReLU fused in A-load) -> spmm -> BN stats
    k_gemm_tf32<<<gg, T>>>(bufB, W1, bufA, NN, HID, 256, 1);
    k_gspmm256<<<NN, HID>>>(bufA, bufB, b1);
    k_bnzero<<<1, HID>>>();
    k_bnstats<<<512, HID>>>(bufB);
    k_bnfin<<<1, HID>>>(g1, be1);

    // ---- layer 2 GEMM (BN1+ReLU fused in A-load) into t40
    k_gemm40<<<gM64, T>>>(bufB, W2, t40, NN, HID);

    // ---- fused 40-channel SpMMs
    float* dst1 = out + NN * OC;
    float* dst2 = out + 2 * NN * OC;
    k_gspmm40t<<<gRW, T>>>(t40, out, b2, lab0, y0, lab1, y2);
    k_gspmm40d<<<gRW, T>>>(y0, y1, y2, y3);
    k_gspmm40d<<<gRW, T>>>(y1, dst1, y3, dst2);
}

// round 9
// speedup vs baseline: 1.5145x; 1.0225x over previous
#include <cuda_runtime.h>
#include <mma.h>
using namespace nvcuda;

#define NN  50000
#define NNP 50048          // 391 * 128, padded row count for unguarded GEMM stores
#define NE  800000
#define HID 256
#define OC  40
#define SB  49             // scan blocks: 49*1024 >= NN

// ---------------- scratch (static device allocations) ---------------------------
__device__ float g_deg[NN];
__device__ float g_dinv[NN];
__device__ int   g_cnt[NN];
__device__ int   g_off[NN + 1];
__device__ int   g_cur[NN];
__device__ int   g_bsum[SB];
__device__ int   g_ccol[NE];
__device__ float g_cw[NE];
__device__ float g_bufA[NNP * HID];
__device__ float g_bufB[NNP * HID];
__device__ float g_t40[NN * OC];
__device__ float g_y0[NN * OC];
__device__ float g_y1[NN * OC];
__device__ float g_y2[NN * OC];
__device__ float g_y3[NN * OC];
__device__ float g_bnsum[HID];
__device__ float g_bnsq[HID];
__device__ float g_scale[HID];
__device__ float g_shift[HID];

// ---------------- normalization + CSR build --------------------------------------
__global__ void k_fillinit(float* degp, int* cntp, int n) {
    int i = blockIdx.x * blockDim.x + threadIdx.x;
    if (i < n) { degp[i] = 1.0f; cntp[i] = 0; }
}

__global__ void k_degcnt(const int* __restrict__ row, const float* __restrict__ w) {
    int e = blockIdx.x * blockDim.x + threadIdx.x;
    if (e < NE) {
        int r = row[e];
        atomicAdd(&g_deg[r], w[e]);
        atomicAdd(&g_cnt[r], 1);
    }
}

__global__ void k_dinv() {
    int i = blockIdx.x * blockDim.x + threadIdx.x;
    if (i < NN) {
        float d = g_deg[i];
        g_dinv[i] = (d > 0.f) ? rsqrtf(fmaxf(d, 1e-12f)) : 0.f;
    }
}

// phase 1: per-block exclusive scan (local), block totals to g_bsum
__global__ void k_scan1() {
    __shared__ int wsum[32];
    int tid = threadIdx.x, lane = tid & 31, wid = tid >> 5;
    int i = blockIdx.x * 1024 + tid;
    int v = (i < NN) ? g_cnt[i] : 0;
    int x = v;
    #pragma unroll
    for (int o = 1; o < 32; o <<= 1) {
        int t = __shfl_up_sync(0xFFFFFFFFu, x, o);
        if (lane >= o) x += t;
    }
    if (lane == 31) wsum[wid] = x;
    __syncthreads();
    if (wid == 0) {
        int s = wsum[lane];
        #pragma unroll
        for (int o = 1; o < 32; o <<= 1) {
            int t = __shfl_up_sync(0xFFFFFFFFu, s, o);
            if (lane >= o) s += t;
        }
        wsum[lane] = s;
    }
    __syncthreads();
    int warpoff = (wid > 0) ? wsum[wid - 1] : 0;
    if (i < NN) g_off[i] = warpoff + x - v;            // local exclusive
    if (tid == 1023) g_bsum[blockIdx.x] = warpoff + x;  // block total
}

// phase 2: serial scan of SB block sums (tiny)
__global__ void k_scan2() {
    int acc = 0;
    for (int b = 0; b < SB; b++) {
        int t = g_bsum[b];
        g_bsum[b] = acc;
        acc += t;
    }
    g_off[NN] = acc;
}

// phase 3: add block offsets, copy to g_cur
__global__ void k_scan3() {
    int i = blockIdx.x * 1024 + threadIdx.x;
    if (i < NN) {
        int v = g_off[i] + g_bsum[blockIdx.x];
        g_off[i] = v;
        g_cur[i] = v;
    }
}

__global__ void k_scatter(const int* __restrict__ row, const int* __restrict__ col,
                          const float* __restrict__ w) {
    int e = blockIdx.x * blockDim.x + threadIdx.x;
    if (e < NE) {
        int r = row[e], c = col[e];
        int p = atomicAdd(&g_cur[r], 1);
        g_ccol[p] = c;
        g_cw[p] = g_dinv[r] * w[e] * g_dinv[c];
    }
}

// ---------------- TF32 tensor-core GEMM: C[M,N] = op(A)[M,K] @ B[K,N] ------------
// block tile 128x64, 8 warps (4 m x 2 n), warp tile 32x32, k chunk 32,
// smem pads 40/72 (measured-good config), NOW double-buffered: register-staged
// global loads, 2-stage smem, ONE barrier per k-iteration.
// bn != 0: A element (channel = k index) transformed relu(a*scale[k]+shift[k]).
__global__ void __launch_bounds__(256) k_gemm_tf32(const float* __restrict__ A,
                                                   const float* __restrict__ B,
                                                   float* __restrict__ C,
                                                   int M, int N, int K, int bn) {
    __shared__ float As[2][128][40];   // [buf][m][k]
    __shared__ float Bs[2][32][72];    // [buf][k][n]
    int bm = blockIdx.x * 128, bnn = blockIdx.y * 64;
    int tid = threadIdx.x;
    int warp = tid >> 5;
    int wm = (warp >> 1) * 32;
    int wn = (warp & 1) * 32;

    // per-thread load coordinates
    int am  = tid >> 1;               // A row within tile (0..127)
    int aks = (tid & 1) * 16;         // A k offset (0 or 16)
    int agr = bm + am;                // global A row
    int bk  = tid >> 3;               // B k within tile (0..31)
    int bn8 = (tid & 7) * 8;          // B n offset

    float4 ar[4];                     // staged A (16 floats)
    float4 br[2];                     // staged B (8 floats)

    // stage k0 = 0
    {
        if (agr < M) {
            const float4* p = (const float4*)&A[(long long)agr * K + aks];
            ar[0] = p[0]; ar[1] = p[1]; ar[2] = p[2]; ar[3] = p[3];
        } else {
            ar[0] = ar[1] = ar[2] = ar[3] = make_float4(0.f, 0.f, 0.f, 0.f);
        }
        const float4* q = (const float4*)&B[(long long)bk * N + bnn + bn8];
        br[0] = q[0]; br[1] = q[1];
    }

    wmma::fragment<wmma::accumulator, 16, 16, 8, float> c00, c01, c10, c11;
    wmma::fill_fragment(c00, 0.f); wmma::fill_fragment(c01, 0.f);
    wmma::fill_fragment(c10, 0.f); wmma::fill_fragment(c11, 0.f);

    int buf = 0;
    for (int k0 = 0; k0 < K; k0 += 32) {
        // commit staged regs into smem[buf] (A with optional BN+ReLU)
        #pragma unroll
        for (int i = 0; i < 4; i++) {
            float4 v = ar[i];
            if (bn) {
                int cc = k0 + aks + i * 4;
                v.x = fmaxf(v.x * g_scale[cc + 0] + g_shift[cc + 0], 0.f);
                v.y = fmaxf(v.y * g_scale[cc + 1] + g_shift[cc + 1], 0.f);
                v.z = fmaxf(v.z * g_scale[cc + 2] + g_shift[cc + 2], 0.f);
                v.w = fmaxf(v.w * g_scale[cc + 3] + g_shift[cc + 3], 0.f);
            }
            As[buf][am][aks + i * 4 + 0] = wmma::__float_to_tf32(v.x);
            As[buf][am][aks + i * 4 + 1] = wmma::__float_to_tf32(v.y);
            As[buf][am][aks + i * 4 + 2] = wmma::__float_to_tf32(v.z);
            As[buf][am][aks + i * 4 + 3] = wmma::__float_to_tf32(v.w);
        }
        #pragma unroll
        for (int i = 0; i < 2; i++) {
            float4 v = br[i];
            Bs[buf][bk][bn8 + i * 4 + 0] = wmma::__float_to_tf32(v.x);
            Bs[buf][bk][bn8 + i * 4 + 1] = wmma::__float_to_tf32(v.y);
            Bs[buf][bk][bn8 + i * 4 + 2] = wmma::__float_to_tf32(v.z);
            Bs[buf][bk][bn8 + i * 4 + 3] = wmma::__float_to_tf32(v.w);
        }
        __syncthreads();

        // stage next tile while computing this one
        int kn = k0 + 32;
        if (kn < K) {
            if (agr < M) {
                const float4* p = (const float4*)&A[(long long)agr * K + kn + aks];
                ar[0] = p[0]; ar[1] = p[1]; ar[2] = p[2]; ar[3] = p[3];
            }
            const float4* q = (const float4*)&B[(long long)(kn + bk) * N + bnn + bn8];
            br[0] = q[0]; br[1] = q[1];
        }

        #pragma unroll
        for (int kk = 0; kk < 32; kk += 8) {
            wmma::fragment<wmma::matrix_a, 16, 16, 8, wmma::precision::tf32, wmma::row_major> a0, a1;
            wmma::fragment<wmma::matrix_b, 16, 16, 8, wmma::precision::tf32, wmma::row_major> b0, b1;
            wmma::load_matrix_sync(a0, &As[buf][wm +  0][kk], 40);
            wmma::load_matrix_sync(a1, &As[buf][wm + 16][kk], 40);
            wmma::load_matrix_sync(b0, &Bs[buf][kk][wn +  0], 72);
            wmma::load_matrix_sync(b1, &Bs[buf][kk][wn + 16], 72);
            wmma::mma_sync(c00, a0, b0, c00);
            wmma::mma_sync(c01, a0, b1, c01);
            wmma::mma_sync(c10, a1, b0, c10);
            wmma::mma_sync(c11, a1, b1, c11);
        }
        buf ^= 1;
    }
    float* cp = &C[(long long)(bm + wm) * N + bnn + wn];
    wmma::store_matrix_sync(cp,               c00, N, wmma::mem_row_major);
    wmma::store_matrix_sync(cp + 16,          c01, N, wmma::mem_row_major);
    wmma::store_matrix_sync(cp + 16 * N,      c10, N, wmma::mem_row_major);
    wmma::store_matrix_sync(cp + 16 * N + 16, c11, N, wmma::mem_row_major);
}

// ---------------- GEMM: C[M,40] = relu(bn(A))[M,K] @ B[K,40] (SIMT) --------------
__global__ void k_gemm40(const float* __restrict__ A, const float* __restrict__ B,
                         float* __restrict__ C, int M, int K) {
    __shared__ float As[64][33];
    __shared__ float Bs[32][40];
    int bm = blockIdx.x * 64;
    int r  = threadIdx.x >> 2;
    int cg = threadIdx.x & 3;
    float acc[10] = {};
    for (int k0 = 0; k0 < K; k0 += 32) {
        int kk = (threadIdx.x & 3) * 8;
        int gr = bm + r;
        #pragma unroll
        for (int i = 0; i < 8; i++) {
            int c = k0 + kk + i;
            float v = (gr < M) ? A[(long long)gr * K + c] : 0.f;
            As[r][kk + i] = fmaxf(v * g_scale[c] + g_shift[c], 0.f);
        }
        for (int i = threadIdx.x; i < 32 * 40; i += 256) {
            int k = i / 40, n = i % 40;
            Bs[k][n] = B[(k0 + k) * 40 + n];
        }
        __syncthreads();
        #pragma unroll
        for (int k = 0; k < 32; k++) {
            float a = As[r][k];
            #pragma unroll
            for (int j = 0; j < 10; j++) acc[j] += a * Bs[k][cg + j * 4];
        }
        __syncthreads();
    }
    int gr = bm + r;
    if (gr < M)
        #pragma unroll
        for (int j = 0; j < 10; j++) C[gr * 40 + cg + j * 4] = acc[j];
}

// ---------------- gather SpMM 256ch: out[r] = d^2*in[r] + bias + sum w*in[col] ---
__global__ void __launch_bounds__(256) k_gspmm256(const float* __restrict__ in,
                                                  float* __restrict__ out,
                                                  const float* __restrict__ bias) {
    __shared__ int   scol[256];
    __shared__ float sw[256];
    int r = blockIdx.x;
    int ch = threadIdx.x;
    int beg = g_off[r], end = g_off[r + 1];
    float d = g_dinv[r];
    float acc = d * d * in[r * HID + ch] + bias[ch];
    for (int j0 = beg; j0 < end; j0 += 256) {
        int m = min(256, end - j0);
        if (ch < m) { scol[ch] = g_ccol[j0 + ch]; sw[ch] = g_cw[j0 + ch]; }
        __syncthreads();
        #pragma unroll 4
        for (int j = 0; j < m; j++)
            acc += sw[j] * in[scol[j] * HID + ch];
        __syncthreads();
    }
    out[r * HID + ch] = acc;
}

// ---------------- 40-channel gather SpMM: triple (features + 2 label chains) -----
__global__ void __launch_bounds__(256) k_gspmm40t(
    const float* __restrict__ in0, float* __restrict__ out0, const float* __restrict__ bias0,
    const float* __restrict__ in1, float* __restrict__ out1,
    const float* __restrict__ in2, float* __restrict__ out2) {
    int r = blockIdx.x * 8 + (threadIdx.x >> 5);
    if (r >= NN) return;
    int lane = threadIdx.x & 31;
    int beg = g_off[r], end = g_off[r + 1];
    float d = g_dinv[r];
    float dd = d * d;
    int rb = r * OC + lane;
    float a0 = dd * in0[rb], a1 = dd * in1[rb], a2 = dd * in2[rb];
    float b0 = 0.f, b1 = 0.f, b2 = 0.f;
    if (lane < 8) {
        b0 = dd * in0[rb + 32]; b1 = dd * in1[rb + 32]; b2 = dd * in2[rb + 32];
    }
    #pragma unroll 2
    for (int j = beg; j < end; j++) {
        int cb = g_ccol[j] * OC + lane;
        float w = g_cw[j];
        a0 += w * in0[cb]; a1 += w * in1[cb]; a2 += w * in2[cb];
        if (lane < 8) {
            b0 += w * in0[cb + 32]; b1 += w * in1[cb + 32]; b2 += w * in2[cb + 32];
        }
    }
    a0 += bias0[lane];
    out0[rb] = a0; out1[rb] = a1; out2[rb] = a2;
    if (lane < 8) {
        b0 += bias0[32 + lane];
        out0[rb + 32] = b0; out1[rb + 32] = b1; out2[rb + 32] = b2;
    }
}

// dual version (two label chains, no bias)
__global__ void __launch_bounds__(256) k_gspmm40d(
    const float* __restrict__ in1, float* __restrict__ out1,
    const float* __restrict__ in2, float* __restrict__ out2) {
    int r = blockIdx.x * 8 + (threadIdx.x >> 5);
    if (r >= NN) return;
    int lane = threadIdx.x & 31;
    int beg = g_off[r], end = g_off[r + 1];
    float d = g_dinv[r];
    float dd = d * d;
    int rb = r * OC + lane;
    float a1 = dd * in1[rb], a2 = dd * in2[rb];
    float b1 = 0.f, b2 = 0.f;
    if (lane < 8) { b1 = dd * in1[rb + 32]; b2 = dd * in2[rb + 32]; }
    #pragma unroll 2
    for (int j = beg; j < end; j++) {
        int cb = g_ccol[j] * OC + lane;
        float w = g_cw[j];
        a1 += w * in1[cb]; a2 += w * in2[cb];
        if (lane < 8) { b1 += w * in1[cb + 32]; b2 += w * in2[cb + 32]; }
    }
    out1[rb] = a1; out2[rb] = a2;
    if (lane < 8) { out1[rb + 32] = b1; out2[rb + 32] = b2; }
}

// ---------------- BatchNorm stats -------------------------------------------------
__global__ void k_bnzero() {
    int c = threadIdx.x;
    g_bnsum[c] = 0.f;
    g_bnsq[c]  = 0.f;
}

__global__ void k_bnstats(const float* __restrict__ h) {
    int c = threadIdx.x;
    float s = 0.f, s2 = 0.f;
    for (int r = blockIdx.x; r < NN; r += gridDim.x) {
        float v = h[r * HID + c];
        s += v;
        s2 += v * v;
    }
    atomicAdd(&g_bnsum[c], s);
    atomicAdd(&g_bnsq[c], s2);
}

__global__ void k_bnfin(const float* __restrict__ gamma, const float* __restrict__ beta) {
    int c = threadIdx.x;
    float mu  = g_bnsum[c] * (1.f / NN);
    float var = g_bnsq[c] * (1.f / NN) - mu * mu;
    float sc  = gamma[c] * rsqrtf(var + 1e-5f);
    g_scale[c] = sc;
    g_shift[c] = beta[c] - mu * sc;
}

// ---------------- host orchestration ----------------------------------------------
extern "C" void kernel_launch(void* const* d_in, const int* in_sizes, int n_in,
                              void* d_out, int out_size) {
    const float* x    = (const float*)d_in[0];
    const int*   ei   = (const int*)d_in[1];
    const int*   row  = ei;
    const int*   col  = ei + NE;
    const float* lab0 = (const float*)d_in[2];
    const float* lab1 = (const float*)d_in[3];
    const float* ew   = (const float*)d_in[4];
    const float* W0   = (const float*)d_in[5];
    const float* b0   = (const float*)d_in[6];
    const float* W1   = (const float*)d_in[7];
    const float* b1   = (const float*)d_in[8];
    const float* W2   = (const float*)d_in[9];
    const float* b2   = (const float*)d_in[10];
    const float* g0   = (const float*)d_in[11];
    const float* be0  = (const float*)d_in[12];
    const float* g1   = (const float*)d_in[13];
    const float* be1  = (const float*)d_in[14];
    float* out = (float*)d_out;

    float *bufA, *bufB, *t40, *y0, *y1, *y2, *y3, *degp;
    int* cntp;
    cudaGetSymbolAddress((void**)&bufA, g_bufA);
    cudaGetSymbolAddress((void**)&bufB, g_bufB);
    cudaGetSymbolAddress((void**)&t40,  g_t40);
    cudaGetSymbolAddress((void**)&y0,   g_y0);
    cudaGetSymbolAddress((void**)&y1,   g_y1);
    cudaGetSymbolAddress((void**)&y2,   g_y2);
    cudaGetSymbolAddress((void**)&y3,   g_y3);
    cudaGetSymbolAddress((void**)&degp, g_deg);
    cudaGetSymbolAddress((void**)&cntp, g_cnt);

    const int T = 256;
    const int gN   = (NN + T - 1) / T;
    const int gE   = (NE + T - 1) / T;
    const int gM64 = (NN + 63) / 64;
    const int gRW  = (NN + 7) / 8;

    // normalization + CSR build (multi-block scan)
    k_fillinit<<<gN, T>>>(degp, cntp, NN);
    k_degcnt<<<gE, T>>>(row, ew);
    k_dinv<<<gN, T>>>();
    k_scan1<<<SB, 1024>>>();
    k_scan2<<<1, 1>>>();
    k_scan3<<<SB, 1024>>>();
    k_scatter<<<gE, T>>>(row, col, ew);

    // ---- layer 0: gemm -> spmm -> BN stats (apply fused into next gemm)
    dim3 gg(NNP / 128, HID / 64);
    k_gemm_tf32<<<gg, T>>>(x, W0, bufA, NN, HID, 512, 0);
    k_gspmm256<<<NN, HID>>>(bufA, bufB, b0);
    k_bnzero<<<1, HID>>>();
    k_bnstats<<<512, HID>>>(bufB);
    k_bnfin<<<1, HID>>>(g0, be0);

    // ---- layer 1: gemm (BN0+ReLU fused in A-load) -> spmm -> BN stats
    k_gemm_tf32<<<gg, T>>>(bufB, W1, bufA, NN, HID, 256, 1);
    k_gspmm256<<<NN, HID>>>(bufA, bufB, b1);
    k_bnzero<<<1, HID>>>();
    k_bnstats<<<512, HID>>>(bufB);
    k_bnfin<<<1, HID>>>(g1, be1);

    // ---- layer 2 GEMM (BN1+ReLU fused in A-load) into t40
    k_gemm40<<<gM64, T>>>(bufB, W2, t40, NN, HID);

    // ---- fused 40-channel SpMMs
    float* dst1 = out + NN * OC;
    float* dst2 = out + 2 * NN * OC;
    k_gspmm40t<<<gRW, T>>>(t40, out, b2, lab0, y0, lab1, y2);
    k_gspmm40d<<<gRW, T>>>(y0, y1, y2, y3);
    k_gspmm40d<<<gRW, T>>>(y1, dst1, y3, dst2);
}

// round 10
// speedup vs baseline: 1.5152x; 1.0004x over previous
#include <cuda_runtime.h>
#include <mma.h>
using namespace nvcuda;

#define NN  50000
#define NNP 50048          // 391 * 128, padded row count for unguarded GEMM stores
#define NE  800000
#define HID 256
#define OC  40
#define SB  49             // scan blocks: 49*1024 >= NN

// ---------------- scratch (static device allocations) ---------------------------
__device__ float g_deg[NN];
__device__ float g_dinv[NN];
__device__ int   g_cnt[NN];
__device__ int   g_off[NN + 1];
__device__ int   g_cur[NN];
__device__ int   g_bsum[SB];
__device__ int   g_ccol[NE];
__device__ float g_cw[NE];
__device__ float g_bufA[NNP * HID];
__device__ float g_bufB[NNP * HID];
__device__ float g_t40[NN * OC];
__device__ float g_y0[NN * OC];
__device__ float g_y1[NN * OC];
__device__ float g_y2[NN * OC];
__device__ float g_y3[NN * OC];
__device__ float g_bnsum[HID];
__device__ float g_bnsq[HID];
__device__ float g_scale[HID];
__device__ float g_shift[HID];

// ---------------- normalization + CSR build --------------------------------------
__global__ void k_fillinit(float* degp, int* cntp, int n) {
    int i = blockIdx.x * blockDim.x + threadIdx.x;
    if (i < n) { degp[i] = 1.0f; cntp[i] = 0; }
}

__global__ void k_degcnt(const int* __restrict__ row, const float* __restrict__ w) {
    int e = blockIdx.x * blockDim.x + threadIdx.x;
    if (e < NE) {
        int r = row[e];
        atomicAdd(&g_deg[r], w[e]);
        atomicAdd(&g_cnt[r], 1);
    }
}

__global__ void k_dinv() {
    int i = blockIdx.x * blockDim.x + threadIdx.x;
    if (i < NN) {
        float d = g_deg[i];
        g_dinv[i] = (d > 0.f) ? rsqrtf(fmaxf(d, 1e-12f)) : 0.f;
    }
}

// phase 1: per-block exclusive scan (local), block totals to g_bsum
__global__ void k_scan1() {
    __shared__ int wsum[32];
    int tid = threadIdx.x, lane = tid & 31, wid = tid >> 5;
    int i = blockIdx.x * 1024 + tid;
    int v = (i < NN) ? g_cnt[i] : 0;
    int x = v;
    #pragma unroll
    for (int o = 1; o < 32; o <<= 1) {
        int t = __shfl_up_sync(0xFFFFFFFFu, x, o);
        if (lane >= o) x += t;
    }
    if (lane == 31) wsum[wid] = x;
    __syncthreads();
    if (wid == 0) {
        int s = wsum[lane];
        #pragma unroll
        for (int o = 1; o < 32; o <<= 1) {
            int t = __shfl_up_sync(0xFFFFFFFFu, s, o);
            if (lane >= o) s += t;
        }
        wsum[lane] = s;
    }
    __syncthreads();
    int warpoff = (wid > 0) ? wsum[wid - 1] : 0;
    if (i < NN) g_off[i] = warpoff + x - v;            // local exclusive
    if (tid == 1023) g_bsum[blockIdx.x] = warpoff + x;  // block total
}

// phase 2: serial scan of SB block sums (tiny)
__global__ void k_scan2() {
    int acc = 0;
    for (int b = 0; b < SB; b++) {
        int t = g_bsum[b];
        g_bsum[b] = acc;
        acc += t;
    }
    g_off[NN] = acc;
}

// phase 3: add block offsets, copy to g_cur
__global__ void k_scan3() {
    int i = blockIdx.x * 1024 + threadIdx.x;
    if (i < NN) {
        int v = g_off[i] + g_bsum[blockIdx.x];
        g_off[i] = v;
        g_cur[i] = v;
    }
}

__global__ void k_scatter(const int* __restrict__ row, const int* __restrict__ col,
                          const float* __restrict__ w) {
    int e = blockIdx.x * blockDim.x + threadIdx.x;
    if (e < NE) {
        int r = row[e], c = col[e];
        int p = atomicAdd(&g_cur[r], 1);
        g_ccol[p] = c;
        g_cw[p] = g_dinv[r] * w[e] * g_dinv[c];
    }
}

// ---------------- TF32 tensor-core GEMM: C[M,N] = op(A)[M,K] @ B[K,N] ------------
// block tile 128x128, 8 warps (4 m x 2 n), warp tile 32x64, k chunk 32.
// A-stride 40 (=8 mod 32, measured-good), B-stride 136 (=8 mod 32), single buffer,
// round-6 loop structure. bn != 0: A transformed relu(a*scale[k]+shift[k]).
__global__ void __launch_bounds__(256) k_gemm_tf32(const float* __restrict__ A,
                                                   const float* __restrict__ B,
                                                   float* __restrict__ C,
                                                   int M, int N, int K, int bn) {
    __shared__ float As[128][40];    // [m][k], k chunk 32
    __shared__ float Bs[32][136];    // [k][n], n chunk 128
    int bm = blockIdx.x * 128, bnn = blockIdx.y * 128;
    int tid = threadIdx.x;
    int warp = tid >> 5;
    int wm = (warp >> 1) * 32;       // 4 warps along m
    int wn = (warp & 1) * 64;        // 2 warps along n

    wmma::fragment<wmma::accumulator, 16, 16, 8, float> c[2][4];
    #pragma unroll
    for (int i = 0; i < 2; i++)
        #pragma unroll
        for (int j = 0; j < 4; j++)
            wmma::fill_fragment(c[i][j], 0.f);

    for (int k0 = 0; k0 < K; k0 += 32) {
        // A tile 128x32: thread -> m = tid>>1, 16 consecutive k
        {
            int m  = tid >> 1;
            int ks = (tid & 1) * 16;
            int gr = bm + m;
            if (gr < M) {
                const float4* p = (const float4*)&A[(long long)gr * K + k0 + ks];
                #pragma unroll
                for (int i = 0; i < 4; i++) {
                    float4 v = p[i];
                    if (bn) {
                        int cc = k0 + ks + i * 4;
                        v.x = fmaxf(v.x * g_scale[cc + 0] + g_shift[cc + 0], 0.f);
                        v.y = fmaxf(v.y * g_scale[cc + 1] + g_shift[cc + 1], 0.f);
                        v.z = fmaxf(v.z * g_scale[cc + 2] + g_shift[cc + 2], 0.f);
                        v.w = fmaxf(v.w * g_scale[cc + 3] + g_shift[cc + 3], 0.f);
                    }
                    As[m][ks + i * 4 + 0] = wmma::__float_to_tf32(v.x);
                    As[m][ks + i * 4 + 1] = wmma::__float_to_tf32(v.y);
                    As[m][ks + i * 4 + 2] = wmma::__float_to_tf32(v.z);
                    As[m][ks + i * 4 + 3] = wmma::__float_to_tf32(v.w);
                }
            } else {
                #pragma unroll
                for (int i = 0; i < 16; i++) As[m][ks + i] = 0.f;
            }
        }
        // B tile 32x128: thread -> k = tid>>3, 16 consecutive n (4 float4)
        {
            int k   = tid >> 3;
            int n16 = (tid & 7) * 16;
            const float4* p = (const float4*)&B[(long long)(k0 + k) * N + bnn + n16];
            #pragma unroll
            for (int i = 0; i < 4; i++) {
                float4 v = p[i];
                Bs[k][n16 + i * 4 + 0] = wmma::__float_to_tf32(v.x);
                Bs[k][n16 + i * 4 + 1] = wmma::__float_to_tf32(v.y);
                Bs[k][n16 + i * 4 + 2] = wmma::__float_to_tf32(v.z);
                Bs[k][n16 + i * 4 + 3] = wmma::__float_to_tf32(v.w);
            }
        }
        __syncthreads();
        #pragma unroll
        for (int kk = 0; kk < 32; kk += 8) {
            wmma::fragment<wmma::matrix_a, 16, 16, 8, wmma::precision::tf32, wmma::row_major> a0, a1;
            wmma::fragment<wmma::matrix_b, 16, 16, 8, wmma::precision::tf32, wmma::row_major> b[4];
            wmma::load_matrix_sync(a0, &As[wm +  0][kk], 40);
            wmma::load_matrix_sync(a1, &As[wm + 16][kk], 40);
            #pragma unroll
            for (int j = 0; j < 4; j++)
                wmma::load_matrix_sync(b[j], &Bs[kk][wn + 16 * j], 136);
            #pragma unroll
            for (int j = 0; j < 4; j++) {
                wmma::mma_sync(c[0][j], a0, b[j], c[0][j]);
                wmma::mma_sync(c[1][j], a1, b[j], c[1][j]);
            }
        }
        __syncthreads();
    }
    #pragma unroll
    for (int i = 0; i < 2; i++)
        #pragma unroll
        for (int j = 0; j < 4; j++)
            wmma::store_matrix_sync(
                &C[(long long)(bm + wm + 16 * i) * N + bnn + wn + 16 * j],
                c[i][j], N, wmma::mem_row_major);
}

// ---------------- GEMM: C[M,40] = relu(bn(A))[M,K] @ B[K,40] (SIMT) --------------
__global__ void k_gemm40(const float* __restrict__ A, const float* __restrict__ B,
                         float* __restrict__ C, int M, int K) {
    __shared__ float As[64][33];
    __shared__ float Bs[32][40];
    int bm = blockIdx.x * 64;
    int r  = threadIdx.x >> 2;
    int cg = threadIdx.x & 3;
    float acc[10] = {};
    for (int k0 = 0; k0 < K; k0 += 32) {
        int kk = (threadIdx.x & 3) * 8;
        int gr = bm + r;
        #pragma unroll
        for (int i = 0; i < 8; i++) {
            int c = k0 + kk + i;
            float v = (gr < M) ? A[(long long)gr * K + c] : 0.f;
            As[r][kk + i] = fmaxf(v * g_scale[c] + g_shift[c], 0.f);
        }
        for (int i = threadIdx.x; i < 32 * 40; i += 256) {
            int k = i / 40, n = i % 40;
            Bs[k][n] = B[(k0 + k) * 40 + n];
        }
        __syncthreads();
        #pragma unroll
        for (int k = 0; k < 32; k++) {
            float a = As[r][k];
            #pragma unroll
            for (int j = 0; j < 10; j++) acc[j] += a * Bs[k][cg + j * 4];
        }
        __syncthreads();
    }
    int gr = bm + r;
    if (gr < M)
        #pragma unroll
        for (int j = 0; j < 10; j++) C[gr * 40 + cg + j * 4] = acc[j];
}

// ---------------- gather SpMM 256ch: out[r] = d^2*in[r] + bias + sum w*in[col] ---
__global__ void __launch_bounds__(256) k_gspmm256(const float* __restrict__ in,
                                                  float* __restrict__ out,
                                                  const float* __restrict__ bias) {
    __shared__ int   scol[256];
    __shared__ float sw[256];
    int r = blockIdx.x;
    int ch = threadIdx.x;
    int beg = g_off[r], end = g_off[r + 1];
    float d = g_dinv[r];
    float acc = d * d * in[r * HID + ch] + bias[ch];
    for (int j0 = beg; j0 < end; j0 += 256) {
        int m = min(256, end - j0);
        if (ch < m) { scol[ch] = g_ccol[j0 + ch]; sw[ch] = g_cw[j0 + ch]; }
        __syncthreads();
        #pragma unroll 4
        for (int j = 0; j < m; j++)
            acc += sw[j] * in[scol[j] * HID + ch];
        __syncthreads();
    }
    out[r * HID + ch] = acc;
}

// ---------------- 40-channel gather SpMM: triple (features + 2 label chains) -----
__global__ void __launch_bounds__(256) k_gspmm40t(
    const float* __restrict__ in0, float* __restrict__ out0, const float* __restrict__ bias0,
    const float* __restrict__ in1, float* __restrict__ out1,
    const float* __restrict__ in2, float* __restrict__ out2) {
    int r = blockIdx.x * 8 + (threadIdx.x >> 5);
    if (r >= NN) return;
    int lane = threadIdx.x & 31;
    int beg = g_off[r], end = g_off[r + 1];
    float d = g_dinv[r];
    float dd = d * d;
    int rb = r * OC + lane;
    float a0 = dd * in0[rb], a1 = dd * in1[rb], a2 = dd * in2[rb];
    float b0 = 0.f, b1 = 0.f, b2 = 0.f;
    if (lane < 8) {
        b0 = dd * in0[rb + 32]; b1 = dd * in1[rb + 32]; b2 = dd * in2[rb + 32];
    }
    #pragma unroll 2
    for (int j = beg; j < end; j++) {
        int cb = g_ccol[j] * OC + lane;
        float w = g_cw[j];
        a0 += w * in0[cb]; a1 += w * in1[cb]; a2 += w * in2[cb];
        if (lane < 8) {
            b0 += w * in0[cb + 32]; b1 += w * in1[cb + 32]; b2 += w * in2[cb + 32];
        }
    }
    a0 += bias0[lane];
    out0[rb] = a0; out1[rb] = a1; out2[rb] = a2;
    if (lane < 8) {
        b0 += bias0[32 + lane];
        out0[rb + 32] = b0; out1[rb + 32] = b1; out2[rb + 32] = b2;
    }
}

// dual version (two label chains, no bias)
__global__ void __launch_bounds__(256) k_gspmm40d(
    const float* __restrict__ in1, float* __restrict__ out1,
    const float* __restrict__ in2, float* __restrict__ out2) {
    int r = blockIdx.x * 8 + (threadIdx.x >> 5);
    if (r >= NN) return;
    int lane = threadIdx.x & 31;
    int beg = g_off[r], end = g_off[r + 1];
    float d = g_dinv[r];
    float dd = d * d;
    int rb = r * OC + lane;
    float a1 = dd * in1[rb], a2 = dd * in2[rb];
    float b1 = 0.f, b2 = 0.f;
    if (lane < 8) { b1 = dd * in1[rb + 32]; b2 = dd * in2[rb + 32]; }
    #pragma unroll 2
    for (int j = beg; j < end; j++) {
        int cb = g_ccol[j] * OC + lane;
        float w = g_cw[j];
        a1 += w * in1[cb]; a2 += w * in2[cb];
        if (lane < 8) { b1 += w * in1[cb + 32]; b2 += w * in2[cb + 32]; }
    }
    out1[rb] = a1; out2[rb] = a2;
    if (lane < 8) { out1[rb + 32] = b1; out2[rb + 32] = b2; }
}

// ---------------- BatchNorm stats -------------------------------------------------
__global__ void k_bnzero() {
    int c = threadIdx.x;
    g_bnsum[c] = 0.f;
    g_bnsq[c]  = 0.f;
}

__global__ void k_bnstats(const float* __restrict__ h) {
    int c = threadIdx.x;
    float s = 0.f, s2 = 0.f;
    for (int r = blockIdx.x; r < NN; r += gridDim.x) {
        float v = h[r * HID + c];
        s += v;
        s2 += v * v;
    }
    atomicAdd(&g_bnsum[c], s);
    atomicAdd(&g_bnsq[c], s2);
}

__global__ void k_bnfin(const float* __restrict__ gamma, const float* __restrict__ beta) {
    int c = threadIdx.x;
    float mu  = g_bnsum[c] * (1.f / NN);
    float var = g_bnsq[c] * (1.f / NN) - mu * mu;
    float sc  = gamma[c] * rsqrtf(var + 1e-5f);
    g_scale[c] = sc;
    g_shift[c] = beta[c] - mu * sc;
}

// ---------------- host orchestration ----------------------------------------------
extern "C" void kernel_launch(void* const* d_in, const int* in_sizes, int n_in,
                              void* d_out, int out_size) {
    const float* x    = (const float*)d_in[0];
    const int*   ei   = (const int*)d_in[1];
    const int*   row  = ei;
    const int*   col  = ei + NE;
    const float* lab0 = (const float*)d_in[2];
    const float* lab1 = (const float*)d_in[3];
    const float* ew   = (const float*)d_in[4];
    const float* W0   = (const float*)d_in[5];
    const float* b0   = (const float*)d_in[6];
    const float* W1   = (const float*)d_in[7];
    const float* b1   = (const float*)d_in[8];
    const float* W2   = (const float*)d_in[9];
    const float* b2   = (const float*)d_in[10];
    const float* g0   = (const float*)d_in[11];
    const float* be0  = (const float*)d_in[12];
    const float* g1   = (const float*)d_in[13];
    const float* be1  = (const float*)d_in[14];
    float* out = (float*)d_out;

    float *bufA, *bufB, *t40, *y0, *y1, *y2, *y3, *degp;
    int* cntp;
    cudaGetSymbolAddress((void**)&bufA, g_bufA);
    cudaGetSymbolAddress((void**)&bufB, g_bufB);
    cudaGetSymbolAddress((void**)&t40,  g_t40);
    cudaGetSymbolAddress((void**)&y0,   g_y0);
    cudaGetSymbolAddress((void**)&y1,   g_y1);
    cudaGetSymbolAddress((void**)&y2,   g_y2);
    cudaGetSymbolAddress((void**)&y3,   g_y3);
    cudaGetSymbolAddress((void**)&degp, g_deg);
    cudaGetSymbolAddress((void**)&cntp, g_cnt);

    const int T = 256;
    const int gN   = (NN + T - 1) / T;
    const int gE   = (NE + T - 1) / T;
    const int gM64 = (NN + 63) / 64;
    const int gRW  = (NN + 7) / 8;

    // normalization + CSR build (multi-block scan)
    k_fillinit<<<gN, T>>>(degp, cntp, NN);
    k_degcnt<<<gE, T>>>(row, ew);
    k_dinv<<<gN, T>>>();
    k_scan1<<<SB, 1024>>>();
    k_scan2<<<1, 1>>>();
    k_scan3<<<SB, 1024>>>();
    k_scatter<<<gE, T>>>(row, col, ew);

    // ---- layer 0: gemm -> spmm -> BN stats (apply fused into next gemm)
    dim3 gg(NNP / 128, HID / 128);
    k_gemm_tf32<<<gg, T>>>(x, W0, bufA, NN, HID, 512, 0);
    k_gspmm256<<<NN, HID>>>(bufA, bufB, b0);
    k_bnzero<<<1, HID>>>();
    k_bnstats<<<512, HID>>>(bufB);
    k_bnfin<<<1, HID>>>(g0, be0);

    // ---- layer 1: gemm (BN0+ReLU fused in A-load) -> spmm -> BN stats
    k_gemm_tf32<<<gg, T>>>(bufB, W1, bufA, NN, HID, 256, 1);
    k_gspmm256<<<NN, HID>>>(bufA, bufB, b1);
    k_bnzero<<<1, HID>>>();
    k_bnstats<<<512, HID>>>(bufB);
    k_bnfin<<<1, HID>>>(g1, be1);

    // ---- layer 2 GEMM (BN1+ReLU fused in A-load) into t40
    k_gemm40<<<gM64, T>>>(bufB, W2, t40, NN, HID);

    // ---- fused 40-channel SpMMs
    float* dst1 = out + NN * OC;
    float* dst2 = out + 2 * NN * OC;
    k_gspmm40t<<<gRW, T>>>(t40, out, b2, lab0, y0, lab1, y2);
    k_gspmm40d<<<gRW, T>>>(y0, y1, y2, y3);
    k_gspmm40d<<<gRW, T>>>(y1, dst1, y3, dst2);
}

// round 11
// speedup vs baseline: 1.7633x; 1.1637x over previous
#include <cuda_runtime.h>
#include <mma.h>
using namespace nvcuda;

#define NN  50000
#define NNP 50048          // 391 * 128, padded row count for unguarded GEMM stores
#define NE  800000
#define HID 256
#define OC  40
#define SB  49             // scan blocks: 49*1024 >= NN

// ---------------- scratch (static device allocations) ---------------------------
__device__ float g_deg[NN];
__device__ float g_dinv[NN];
__device__ int   g_cnt[NN];
__device__ int   g_off[NN + 1];
__device__ int   g_cur[NN];
__device__ int   g_bsum[SB];
__device__ int   g_ccol[NE];
__device__ float g_cw[NE];
__device__ float g_bufA[NNP * HID];
__device__ float g_bufB[NNP * HID];
__device__ float g_t40[NN * OC];
__device__ float g_y0[NN * OC];
__device__ float g_y1[NN * OC];
__device__ float g_y2[NN * OC];
__device__ float g_y3[NN * OC];
__device__ float g_bnsum[HID];
__device__ float g_bnsq[HID];
__device__ float g_scale[HID];
__device__ float g_shift[HID];

// ---------------- normalization + CSR build --------------------------------------
__global__ void k_fillinit(float* degp, int* cntp, int n) {
    int i = blockIdx.x * blockDim.x + threadIdx.x;
    if (i < n) { degp[i] = 1.0f; cntp[i] = 0; }
}

__global__ void k_degcnt(const int* __restrict__ row, const float* __restrict__ w) {
    int e = blockIdx.x * blockDim.x + threadIdx.x;
    if (e < NE) {
        int r = row[e];
        atomicAdd(&g_deg[r], w[e]);
        atomicAdd(&g_cnt[r], 1);
    }
}

__global__ void k_dinv() {
    int i = blockIdx.x * blockDim.x + threadIdx.x;
    if (i < NN) {
        float d = g_deg[i];
        g_dinv[i] = (d > 0.f) ? rsqrtf(fmaxf(d, 1e-12f)) : 0.f;
    }
}

// phase 1: per-block exclusive scan (local), block totals to g_bsum
__global__ void k_scan1() {
    __shared__ int wsum[32];
    int tid = threadIdx.x, lane = tid & 31, wid = tid >> 5;
    int i = blockIdx.x * 1024 + tid;
    int v = (i < NN) ? g_cnt[i] : 0;
    int x = v;
    #pragma unroll
    for (int o = 1; o < 32; o <<= 1) {
        int t = __shfl_up_sync(0xFFFFFFFFu, x, o);
        if (lane >= o) x += t;
    }
    if (lane == 31) wsum[wid] = x;
    __syncthreads();
    if (wid == 0) {
        int s = wsum[lane];
        #pragma unroll
        for (int o = 1; o < 32; o <<= 1) {
            int t = __shfl_up_sync(0xFFFFFFFFu, s, o);
            if (lane >= o) s += t;
        }
        wsum[lane] = s;
    }
    __syncthreads();
    int warpoff = (wid > 0) ? wsum[wid - 1] : 0;
    if (i < NN) g_off[i] = warpoff + x - v;            // local exclusive
    if (tid == 1023) g_bsum[blockIdx.x] = warpoff + x;  // block total
}

// phase 2: serial scan of SB block sums (tiny)
__global__ void k_scan2() {
    int acc = 0;
    for (int b = 0; b < SB; b++) {
        int t = g_bsum[b];
        g_bsum[b] = acc;
        acc += t;
    }
    g_off[NN] = acc;
}

// phase 3: add block offsets, copy to g_cur
__global__ void k_scan3() {
    int i = blockIdx.x * 1024 + threadIdx.x;
    if (i < NN) {
        int v = g_off[i] + g_bsum[blockIdx.x];
        g_off[i] = v;
        g_cur[i] = v;
    }
}

__global__ void k_scatter(const int* __restrict__ row, const int* __restrict__ col,
                          const float* __restrict__ w) {
    int e = blockIdx.x * blockDim.x + threadIdx.x;
    if (e < NE) {
        int r = row[e], c = col[e];
        int p = atomicAdd(&g_cur[r], 1);
        g_ccol[p] = c;
        g_cw[p] = g_dinv[r] * w[e] * g_dinv[c];
    }
}

// ---------------- TF32 tensor-core GEMM: C[M,N] = op(A)[M,K] @ B[K,N] ------------
// block tile 128x128, 8 warps (4 m x 2 n), warp tile 32x64, k chunk 32.
// bn != 0: A element (channel = k index) transformed relu(a*scale[k]+shift[k]).
__global__ void __launch_bounds__(256) k_gemm_tf32(const float* __restrict__ A,
                                                   const float* __restrict__ B,
                                                   float* __restrict__ C,
                                                   int M, int N, int K, int bn) {
    __shared__ float As[128][40];    // [m][k], k chunk 32
    __shared__ float Bs[32][136];    // [k][n], n chunk 128
    int bm = blockIdx.x * 128, bnn = blockIdx.y * 128;
    int tid = threadIdx.x;
    int warp = tid >> 5;
    int wm = (warp >> 1) * 32;       // 4 warps along m
    int wn = (warp & 1) * 64;        // 2 warps along n

    wmma::fragment<wmma::accumulator, 16, 16, 8, float> c[2][4];
    #pragma unroll
    for (int i = 0; i < 2; i++)
        #pragma unroll
        for (int j = 0; j < 4; j++)
            wmma::fill_fragment(c[i][j], 0.f);

    for (int k0 = 0; k0 < K; k0 += 32) {
        {
            int m  = tid >> 1;
            int ks = (tid & 1) * 16;
            int gr = bm + m;
            if (gr < M) {
                const float4* p = (const float4*)&A[(long long)gr * K + k0 + ks];
                #pragma unroll
                for (int i = 0; i < 4; i++) {
                    float4 v = p[i];
                    if (bn) {
                        int cc = k0 + ks + i * 4;
                        v.x = fmaxf(v.x * g_scale[cc + 0] + g_shift[cc + 0], 0.f);
                        v.y = fmaxf(v.y * g_scale[cc + 1] + g_shift[cc + 1], 0.f);
                        v.z = fmaxf(v.z * g_scale[cc + 2] + g_shift[cc + 2], 0.f);
                        v.w = fmaxf(v.w * g_scale[cc + 3] + g_shift[cc + 3], 0.f);
                    }
                    As[m][ks + i * 4 + 0] = wmma::__float_to_tf32(v.x);
                    As[m][ks + i * 4 + 1] = wmma::__float_to_tf32(v.y);
                    As[m][ks + i * 4 + 2] = wmma::__float_to_tf32(v.z);
                    As[m][ks + i * 4 + 3] = wmma::__float_to_tf32(v.w);
                }
            } else {
                #pragma unroll
                for (int i = 0; i < 16; i++) As[m][ks + i] = 0.f;
            }
        }
        {
            int k   = tid >> 3;
            int n16 = (tid & 7) * 16;
            const float4* p = (const float4*)&B[(long long)(k0 + k) * N + bnn + n16];
            #pragma unroll
            for (int i = 0; i < 4; i++) {
                float4 v = p[i];
                Bs[k][n16 + i * 4 + 0] = wmma::__float_to_tf32(v.x);
                Bs[k][n16 + i * 4 + 1] = wmma::__float_to_tf32(v.y);
                Bs[k][n16 + i * 4 + 2] = wmma::__float_to_tf32(v.z);
                Bs[k][n16 + i * 4 + 3] = wmma::__float_to_tf32(v.w);
            }
        }
        __syncthreads();
        #pragma unroll
        for (int kk = 0; kk < 32; kk += 8) {
            wmma::fragment<wmma::matrix_a, 16, 16, 8, wmma::precision::tf32, wmma::row_major> a0, a1;
            wmma::fragment<wmma::matrix_b, 16, 16, 8, wmma::precision::tf32, wmma::row_major> b[4];
            wmma::load_matrix_sync(a0, &As[wm +  0][kk], 40);
            wmma::load_matrix_sync(a1, &As[wm + 16][kk], 40);
            #pragma unroll
            for (int j = 0; j < 4; j++)
                wmma::load_matrix_sync(b[j], &Bs[kk][wn + 16 * j], 136);
            #pragma unroll
            for (int j = 0; j < 4; j++) {
                wmma::mma_sync(c[0][j], a0, b[j], c[0][j]);
                wmma::mma_sync(c[1][j], a1, b[j], c[1][j]);
            }
        }
        __syncthreads();
    }
    #pragma unroll
    for (int i = 0; i < 2; i++)
        #pragma unroll
        for (int j = 0; j < 4; j++)
            wmma::store_matrix_sync(
                &C[(long long)(bm + wm + 16 * i) * N + bnn + wn + 16 * j],
                c[i][j], N, wmma::mem_row_major);
}

// ---------------- GEMM: C[M,40] = relu(bn(A))[M,K] @ B[K,40] (SIMT) --------------
__global__ void k_gemm40(const float* __restrict__ A, const float* __restrict__ B,
                         float* __restrict__ C, int M, int K) {
    __shared__ float As[64][33];
    __shared__ float Bs[32][40];
    int bm = blockIdx.x * 64;
    int r  = threadIdx.x >> 2;
    int cg = threadIdx.x & 3;
    float acc[10] = {};
    for (int k0 = 0; k0 < K; k0 += 32) {
        int kk = (threadIdx.x & 3) * 8;
        int gr = bm + r;
        #pragma unroll
        for (int i = 0; i < 8; i++) {
            int c = k0 + kk + i;
            float v = (gr < M) ? A[(long long)gr * K + c] : 0.f;
            As[r][kk + i] = fmaxf(v * g_scale[c] + g_shift[c], 0.f);
        }
        for (int i = threadIdx.x; i < 32 * 40; i += 256) {
            int k = i / 40, n = i % 40;
            Bs[k][n] = B[(k0 + k) * 40 + n];
        }
        __syncthreads();
        #pragma unroll
        for (int k = 0; k < 32; k++) {
            float a = As[r][k];
            #pragma unroll
            for (int j = 0; j < 10; j++) acc[j] += a * Bs[k][cg + j * 4];
        }
        __syncthreads();
    }
    int gr = bm + r;
    if (gr < M)
        #pragma unroll
        for (int j = 0; j < 10; j++) C[gr * 40 + cg + j * 4] = acc[j];
}

// ---------------- gather SpMM 256ch (float4, no smem, no barriers) ---------------
// block = 4 rows x 64 threads; each thread accumulates 4 channels as float4.
// out[r] = d^2*in[r] + bias + sum_e w_e * in[col_e]
__global__ void __launch_bounds__(256) k_gspmm256(const float* __restrict__ in,
                                                  float* __restrict__ out,
                                                  const float* __restrict__ bias) {
    int r    = blockIdx.x * 4 + (threadIdx.x >> 6);   // NN divisible by 4
    int lane = threadIdx.x & 63;                      // channel group (4 ch)
    int beg = g_off[r], end = g_off[r + 1];
    float d = g_dinv[r];
    float dd = d * d;
    const float4* in4 = (const float4*)in;
    float4 acc = in4[r * 64 + lane];
    float4 bv  = ((const float4*)bias)[lane];
    acc.x = dd * acc.x + bv.x;
    acc.y = dd * acc.y + bv.y;
    acc.z = dd * acc.z + bv.z;
    acc.w = dd * acc.w + bv.w;
    #pragma unroll 2
    for (int j = beg; j < end; j++) {
        int   c = __ldg(&g_ccol[j]);
        float w = __ldg(&g_cw[j]);
        float4 v = in4[c * 64 + lane];
        acc.x += w * v.x;
        acc.y += w * v.y;
        acc.z += w * v.z;
        acc.w += w * v.w;
    }
    ((float4*)out)[r * 64 + lane] = acc;
}

// ---------------- 40-channel gather SpMM: triple (features + 2 label chains) -----
__global__ void __launch_bounds__(256) k_gspmm40t(
    const float* __restrict__ in0, float* __restrict__ out0, const float* __restrict__ bias0,
    const float* __restrict__ in1, float* __restrict__ out1,
    const float* __restrict__ in2, float* __restrict__ out2) {
    int r = blockIdx.x * 8 + (threadIdx.x >> 5);
    if (r >= NN) return;
    int lane = threadIdx.x & 31;
    int beg = g_off[r], end = g_off[r + 1];
    float d = g_dinv[r];
    float dd = d * d;
    int rb = r * OC + lane;
    float a0 = dd * in0[rb], a1 = dd * in1[rb], a2 = dd * in2[rb];
    float b0 = 0.f, b1 = 0.f, b2 = 0.f;
    if (lane < 8) {
        b0 = dd * in0[rb + 32]; b1 = dd * in1[rb + 32]; b2 = dd * in2[rb + 32];
    }
    #pragma unroll 2
    for (int j = beg; j < end; j++) {
        int cb = g_ccol[j] * OC + lane;
        float w = g_cw[j];
        a0 += w * in0[cb]; a1 += w * in1[cb]; a2 += w * in2[cb];
        if (lane < 8) {
            b0 += w * in0[cb + 32]; b1 += w * in1[cb + 32]; b2 += w * in2[cb + 32];
        }
    }
    a0 += bias0[lane];
    out0[rb] = a0; out1[rb] = a1; out2[rb] = a2;
    if (lane < 8) {
        b0 += bias0[32 + lane];
        out0[rb + 32] = b0; out1[rb + 32] = b1; out2[rb + 32] = b2;
    }
}

// dual version (two label chains, no bias)
__global__ void __launch_bounds__(256) k_gspmm40d(
    const float* __restrict__ in1, float* __restrict__ out1,
    const float* __restrict__ in2, float* __restrict__ out2) {
    int r = blockIdx.x * 8 + (threadIdx.x >> 5);
    if (r >= NN) return;
    int lane = threadIdx.x & 31;
    int beg = g_off[r], end = g_off[r + 1];
    float d = g_dinv[r];
    float dd = d * d;
    int rb = r * OC + lane;
    float a1 = dd * in1[rb], a2 = dd * in2[rb];
    float b1 = 0.f, b2 = 0.f;
    if (lane < 8) { b1 = dd * in1[rb + 32]; b2 = dd * in2[rb + 32]; }
    #pragma unroll 2
    for (int j = beg; j < end; j++) {
        int cb = g_ccol[j] * OC + lane;
        float w = g_cw[j];
        a1 += w * in1[cb]; a2 += w * in2[cb];
        if (lane < 8) { b1 += w * in1[cb + 32]; b2 += w * in2[cb + 32]; }
    }
    out1[rb] = a1; out2[rb] = a2;
    if (lane < 8) { out1[rb + 32] = b1; out2[rb + 32] = b2; }
}

// ---------------- BatchNorm stats -------------------------------------------------
__global__ void k_bnzero() {
    int c = threadIdx.x;
    g_bnsum[c] = 0.f;
    g_bnsq[c]  = 0.f;
}

__global__ void k_bnstats(const float* __restrict__ h) {
    int c = threadIdx.x;
    float s = 0.f, s2 = 0.f;
    for (int r = blockIdx.x; r < NN; r += gridDim.x) {
        float v = h[r * HID + c];
        s += v;
        s2 += v * v;
    }
    atomicAdd(&g_bnsum[c], s);
    atomicAdd(&g_bnsq[c], s2);
}

__global__ void k_bnfin(const float* __restrict__ gamma, const float* __restrict__ beta) {
    int c = threadIdx.x;
    float mu  = g_bnsum[c] * (1.f / NN);
    float var = g_bnsq[c] * (1.f / NN) - mu * mu;
    float sc  = gamma[c] * rsqrtf(var + 1e-5f);
    g_scale[c] = sc;
    g_shift[c] = beta[c] - mu * sc;
}

// ---------------- host orchestration ----------------------------------------------
extern "C" void kernel_launch(void* const* d_in, const int* in_sizes, int n_in,
                              void* d_out, int out_size) {
    const float* x    = (const float*)d_in[0];
    const int*   ei   = (const int*)d_in[1];
    const int*   row  = ei;
    const int*   col  = ei + NE;
    const float* lab0 = (const float*)d_in[2];
    const float* lab1 = (const float*)d_in[3];
    const float* ew   = (const float*)d_in[4];
    const float* W0   = (const float*)d_in[5];
    const float* b0   = (const float*)d_in[6];
    const float* W1   = (const float*)d_in[7];
    const float* b1   = (const float*)d_in[8];
    const float* W2   = (const float*)d_in[9];
    const float* b2   = (const float*)d_in[10];
    const float* g0   = (const float*)d_in[11];
    const float* be0  = (const float*)d_in[12];
    const float* g1   = (const float*)d_in[13];
    const float* be1  = (const float*)d_in[14];
    float* out = (float*)d_out;

    float *bufA, *bufB, *t40, *y0, *y1, *y2, *y3, *degp;
    int* cntp;
    cudaGetSymbolAddress((void**)&bufA, g_bufA);
    cudaGetSymbolAddress((void**)&bufB, g_bufB);
    cudaGetSymbolAddress((void**)&t40,  g_t40);
    cudaGetSymbolAddress((void**)&y0,   g_y0);
    cudaGetSymbolAddress((void**)&y1,   g_y1);
    cudaGetSymbolAddress((void**)&y2,   g_y2);
    cudaGetSymbolAddress((void**)&y3,   g_y3);
    cudaGetSymbolAddress((void**)&degp, g_deg);
    cudaGetSymbolAddress((void**)&cntp, g_cnt);

    const int T = 256;
    const int gN   = (NN + T - 1) / T;
    const int gE   = (NE + T - 1) / T;
    const int gM64 = (NN + 63) / 64;
    const int gRW  = (NN + 7) / 8;

    // build prologue; gemm0 placed 4th so ncu (-s 5 -c 1) profiles it next round
    dim3 gg(NNP / 128, HID / 128);
    k_fillinit<<<gN, T>>>(degp, cntp, NN);
    k_degcnt<<<gE, T>>>(row, ew);
    k_dinv<<<gN, T>>>();
    k_gemm_tf32<<<gg, T>>>(x, W0, bufA, NN, HID, 512, 0);   // 4th launch (profiled)
    k_scan1<<<SB, 1024>>>();
    k_scan2<<<1, 1>>>();
    k_scan3<<<SB, 1024>>>();
    k_scatter<<<gE, T>>>(row, col, ew);

    // ---- layer 0 epilogue: spmm -> BN stats (apply fused into next gemm)
    k_gspmm256<<<NN / 4, T>>>(bufA, bufB, b0);
    k_bnzero<<<1, HID>>>();
    k_bnstats<<<512, HID>>>(bufB);
    k_bnfin<<<1, HID>>>(g0, be0);

    // ---- layer 1: gemm (BN0+ReLU fused in A-load) -> spmm -> BN stats
    k_gemm_tf32<<<gg, T>>>(bufB, W1, bufA, NN, HID, 256, 1);
    k_gspmm256<<<NN / 4, T>>>(bufA, bufB, b1);
    k_bnzero<<<1, HID>>>();
    k_bnstats<<<512, HID>>>(bufB);
    k_bnfin<<<1, HID>>>(g1, be1);

    // ---- layer 2 GEMM (BN1+ReLU fused in A-load) into t40
    k_gemm40<<<gM64, T>>>(bufB, W2, t40, NN, HID);

    // ---- fused 40-channel SpMMs
    float* dst1 = out + NN * OC;
    float* dst2 = out + 2 * NN * OC;
    k_gspmm40t<<<gRW, T>>>(t40, out, b2, lab0, y0, lab1, y2);
    k_gspmm40d<<<gRW, T>>>(y0, y1, y2, y3);
    k_gspmm40d<<<gRW, T>>>(y1, dst1, y3, dst2);
}

// round 12
// speedup vs baseline: 1.8152x; 1.0295x over previous
#include <cuda_runtime.h>
#include <mma.h>
using namespace nvcuda;

#define NN  50000
#define NNP 50048          // 391 * 128, padded row count for unguarded GEMM stores
#define NE  800000
#define HID 256
#define OC  40
#define SB  49             // scan blocks: 49*1024 >= NN

// ---------------- scratch (static device allocations) ---------------------------
__device__ float g_deg[NN];
__device__ float g_dinv[NN];
__device__ int   g_cnt[NN];
__device__ int   g_off[NN + 1];
__device__ int   g_cur[NN];
__device__ int   g_bsum[SB];
__device__ int   g_ccol[NE];
__device__ float g_cw[NE];
__device__ float g_bufA[NNP * HID];
__device__ float g_bufB[NNP * HID];
__device__ float g_t40[NN * OC];
__device__ float g_y0[NN * OC];
__device__ float g_y1[NN * OC];
__device__ float g_y2[NN * OC];
__device__ float g_y3[NN * OC];
__device__ float g_bnsum[HID];
__device__ float g_bnsq[HID];
__device__ float g_scale[HID];
__device__ float g_shift[HID];

// ---------------- normalization + CSR build --------------------------------------
__global__ void k_fillinit(float* degp, int* cntp, int n) {
    int i = blockIdx.x * blockDim.x + threadIdx.x;
    if (i < n) { degp[i] = 1.0f; cntp[i] = 0; }
}

__global__ void k_degcnt(const int* __restrict__ row, const float* __restrict__ w) {
    int e = blockIdx.x * blockDim.x + threadIdx.x;
    if (e < NE) {
        int r = row[e];
        atomicAdd(&g_deg[r], w[e]);
        atomicAdd(&g_cnt[r], 1);
    }
}

__global__ void k_dinv() {
    int i = blockIdx.x * blockDim.x + threadIdx.x;
    if (i < NN) {
        float d = g_deg[i];
        g_dinv[i] = (d > 0.f) ? rsqrtf(fmaxf(d, 1e-12f)) : 0.f;
    }
}

// phase 1: per-block exclusive scan (local), block totals to g_bsum
__global__ void k_scan1() {
    __shared__ int wsum[32];
    int tid = threadIdx.x, lane = tid & 31, wid = tid >> 5;
    int i = blockIdx.x * 1024 + tid;
    int v = (i < NN) ? g_cnt[i] : 0;
    int x = v;
    #pragma unroll
    for (int o = 1; o < 32; o <<= 1) {
        int t = __shfl_up_sync(0xFFFFFFFFu, x, o);
        if (lane >= o) x += t;
    }
    if (lane == 31) wsum[wid] = x;
    __syncthreads();
    if (wid == 0) {
        int s = wsum[lane];
        #pragma unroll
        for (int o = 1; o < 32; o <<= 1) {
            int t = __shfl_up_sync(0xFFFFFFFFu, s, o);
            if (lane >= o) s += t;
        }
        wsum[lane] = s;
    }
    __syncthreads();
    int warpoff = (wid > 0) ? wsum[wid - 1] : 0;
    if (i < NN) g_off[i] = warpoff + x - v;            // local exclusive
    if (tid == 1023) g_bsum[blockIdx.x] = warpoff + x;  // block total
}

// phase 2: serial scan of SB block sums (tiny)
__global__ void k_scan2() {
    int acc = 0;
    for (int b = 0; b < SB; b++) {
        int t = g_bsum[b];
        g_bsum[b] = acc;
        acc += t;
    }
    g_off[NN] = acc;
}

// phase 3: add block offsets, copy to g_cur
__global__ void k_scan3() {
    int i = blockIdx.x * 1024 + threadIdx.x;
    if (i < NN) {
        int v = g_off[i] + g_bsum[blockIdx.x];
        g_off[i] = v;
        g_cur[i] = v;
    }
}

__global__ void k_scatter(const int* __restrict__ row, const int* __restrict__ col,
                          const float* __restrict__ w) {
    int e = blockIdx.x * blockDim.x + threadIdx.x;
    if (e < NE) {
        int r = row[e], c = col[e];
        int p = atomicAdd(&g_cur[r], 1);
        g_ccol[p] = c;
        g_cw[p] = g_dinv[r] * w[e] * g_dinv[c];
    }
}

// ---------------- TF32 tensor-core GEMM: C[M,N] = op(A)[M,K] @ B[K,N] ------------
// block tile 128x128, 8 warps (4 m x 2 n), warp tile 32x64, k chunk 32.
// bn != 0: A element (channel = k index) transformed relu(a*scale[k]+shift[k]).
__global__ void __launch_bounds__(256) k_gemm_tf32(const float* __restrict__ A,
                                                   const float* __restrict__ B,
                                                   float* __restrict__ C,
                                                   int M, int N, int K, int bn) {
    __shared__ float As[128][40];    // [m][k], k chunk 32
    __shared__ float Bs[32][136];    // [k][n], n chunk 128
    int bm = blockIdx.x * 128, bnn = blockIdx.y * 128;
    int tid = threadIdx.x;
    int warp = tid >> 5;
    int wm = (warp >> 1) * 32;       // 4 warps along m
    int wn = (warp & 1) * 64;        // 2 warps along n

    wmma::fragment<wmma::accumulator, 16, 16, 8, float> c[2][4];
    #pragma unroll
    for (int i = 0; i < 2; i++)
        #pragma unroll
        for (int j = 0; j < 4; j++)
            wmma::fill_fragment(c[i][j], 0.f);

    for (int k0 = 0; k0 < K; k0 += 32) {
        {
            int m  = tid >> 1;
            int ks = (tid & 1) * 16;
            int gr = bm + m;
            if (gr < M) {
                const float4* p = (const float4*)&A[(long long)gr * K + k0 + ks];
                #pragma unroll
                for (int i = 0; i < 4; i++) {
                    float4 v = p[i];
                    if (bn) {
                        int cc = k0 + ks + i * 4;
                        v.x = fmaxf(v.x * g_scale[cc + 0] + g_shift[cc + 0], 0.f);
                        v.y = fmaxf(v.y * g_scale[cc + 1] + g_shift[cc + 1], 0.f);
                        v.z = fmaxf(v.z * g_scale[cc + 2] + g_shift[cc + 2], 0.f);
                        v.w = fmaxf(v.w * g_scale[cc + 3] + g_shift[cc + 3], 0.f);
                    }
                    As[m][ks + i * 4 + 0] = wmma::__float_to_tf32(v.x);
                    As[m][ks + i * 4 + 1] = wmma::__float_to_tf32(v.y);
                    As[m][ks + i * 4 + 2] = wmma::__float_to_tf32(v.z);
                    As[m][ks + i * 4 + 3] = wmma::__float_to_tf32(v.w);
                }
            } else {
                #pragma unroll
                for (int i = 0; i < 16; i++) As[m][ks + i] = 0.f;
            }
        }
        {
            int k   = tid >> 3;
            int n16 = (tid & 7) * 16;
            const float4* p = (const float4*)&B[(long long)(k0 + k) * N + bnn + n16];
            #pragma unroll
            for (int i = 0; i < 4; i++) {
                float4 v = p[i];
                Bs[k][n16 + i * 4 + 0] = wmma::__float_to_tf32(v.x);
                Bs[k][n16 + i * 4 + 1] = wmma::__float_to_tf32(v.y);
                Bs[k][n16 + i * 4 + 2] = wmma::__float_to_tf32(v.z);
                Bs[k][n16 + i * 4 + 3] = wmma::__float_to_tf32(v.w);
            }
        }
        __syncthreads();
        #pragma unroll
        for (int kk = 0; kk < 32; kk += 8) {
            wmma::fragment<wmma::matrix_a, 16, 16, 8, wmma::precision::tf32, wmma::row_major> a0, a1;
            wmma::fragment<wmma::matrix_b, 16, 16, 8, wmma::precision::tf32, wmma::row_major> b[4];
            wmma::load_matrix_sync(a0, &As[wm +  0][kk], 40);
            wmma::load_matrix_sync(a1, &As[wm + 16][kk], 40);
            #pragma unroll
            for (int j = 0; j < 4; j++)
                wmma::load_matrix_sync(b[j], &Bs[kk][wn + 16 * j], 136);
            #pragma unroll
            for (int j = 0; j < 4; j++) {
                wmma::mma_sync(c[0][j], a0, b[j], c[0][j]);
                wmma::mma_sync(c[1][j], a1, b[j], c[1][j]);
            }
        }
        __syncthreads();
    }
    #pragma unroll
    for (int i = 0; i < 2; i++)
        #pragma unroll
        for (int j = 0; j < 4; j++)
            wmma::store_matrix_sync(
                &C[(long long)(bm + wm + 16 * i) * N + bnn + wn + 16 * j],
                c[i][j], N, wmma::mem_row_major);
}

// ---------------- GEMM: C[M,40] = relu(bn(A))[M,K] @ B[K,40] (SIMT) --------------
__global__ void k_gemm40(const float* __restrict__ A, const float* __restrict__ B,
                         float* __restrict__ C, int M, int K) {
    __shared__ float As[64][33];
    __shared__ float Bs[32][40];
    int bm = blockIdx.x * 64;
    int r  = threadIdx.x >> 2;
    int cg = threadIdx.x & 3;
    float acc[10] = {};
    for (int k0 = 0; k0 < K; k0 += 32) {
        int kk = (threadIdx.x & 3) * 8;
        int gr = bm + r;
        #pragma unroll
        for (int i = 0; i < 8; i++) {
            int c = k0 + kk + i;
            float v = (gr < M) ? A[(long long)gr * K + c] : 0.f;
            As[r][kk + i] = fmaxf(v * g_scale[c] + g_shift[c], 0.f);
        }
        for (int i = threadIdx.x; i < 32 * 40; i += 256) {
            int k = i / 40, n = i % 40;
            Bs[k][n] = B[(k0 + k) * 40 + n];
        }
        __syncthreads();
        #pragma unroll
        for (int k = 0; k < 32; k++) {
            float a = As[r][k];
            #pragma unroll
            for (int j = 0; j < 10; j++) acc[j] += a * Bs[k][cg + j * 4];
        }
        __syncthreads();
    }
    int gr = bm + r;
    if (gr < M)
        #pragma unroll
        for (int j = 0; j < 10; j++) C[gr * 40 + cg + j * 4] = acc[j];
}

// ---------------- gather SpMM 256ch (float4, no smem, no barriers) ---------------
__global__ void __launch_bounds__(256) k_gspmm256(const float* __restrict__ in,
                                                  float* __restrict__ out,
                                                  const float* __restrict__ bias) {
    int r    = blockIdx.x * 4 + (threadIdx.x >> 6);   // NN divisible by 4
    int lane = threadIdx.x & 63;                      // channel group (4 ch)
    int beg = g_off[r], end = g_off[r + 1];
    float d = g_dinv[r];
    float dd = d * d;
    const float4* in4 = (const float4*)in;
    float4 acc = in4[r * 64 + lane];
    float4 bv  = ((const float4*)bias)[lane];
    acc.x = dd * acc.x + bv.x;
    acc.y = dd * acc.y + bv.y;
    acc.z = dd * acc.z + bv.z;
    acc.w = dd * acc.w + bv.w;
    #pragma unroll 2
    for (int j = beg; j < end; j++) {
        int   c = __ldg(&g_ccol[j]);
        float w = __ldg(&g_cw[j]);
        float4 v = in4[c * 64 + lane];
        acc.x += w * v.x;
        acc.y += w * v.y;
        acc.z += w * v.z;
        acc.w += w * v.w;
    }
    ((float4*)out)[r * 64 + lane] = acc;
}

// ---------------- 40-channel gather SpMM, float4 lanes ---------------------------
// warp per row; lane = matrix * 10 + quad (triple: 30 lanes, dual: 20 lanes).
// out_m[r] = d^2*in_m[r] (+bias for m==0 in triple) + sum_e w_e * in_m[col_e]
__global__ void __launch_bounds__(256) k_gspmm40t(
    const float* __restrict__ in0, float* __restrict__ out0, const float* __restrict__ bias0,
    const float* __restrict__ in1, float* __restrict__ out1,
    const float* __restrict__ in2, float* __restrict__ out2) {
    int r = blockIdx.x * 8 + (threadIdx.x >> 5);
    if (r >= NN) return;
    int lane = threadIdx.x & 31;
    if (lane >= 30) return;
    int m = (lane >= 20) ? 2 : (lane >= 10 ? 1 : 0);
    int q = lane - m * 10;
    const float4* in4 = (const float4*)(m == 0 ? in0 : (m == 1 ? in1 : in2));
    float4* out4      = (float4*)(m == 0 ? out0 : (m == 1 ? out1 : out2));
    int beg = g_off[r], end = g_off[r + 1];
    float d = g_dinv[r];
    float dd = d * d;
    float4 acc = in4[r * 10 + q];
    acc.x *= dd; acc.y *= dd; acc.z *= dd; acc.w *= dd;
    if (m == 0) {
        float4 bv = ((const float4*)bias0)[q];
        acc.x += bv.x; acc.y += bv.y; acc.z += bv.z; acc.w += bv.w;
    }
    #pragma unroll 4
    for (int j = beg; j < end; j++) {
        int   c = __ldg(&g_ccol[j]);
        float w = __ldg(&g_cw[j]);
        float4 v = in4[c * 10 + q];
        acc.x += w * v.x;
        acc.y += w * v.y;
        acc.z += w * v.z;
        acc.w += w * v.w;
    }
    out4[r * 10 + q] = acc;
}

__global__ void __launch_bounds__(256) k_gspmm40d(
    const float* __restrict__ in1, float* __restrict__ out1,
    const float* __restrict__ in2, float* __restrict__ out2) {
    int r = blockIdx.x * 8 + (threadIdx.x >> 5);
    if (r >= NN) return;
    int lane = threadIdx.x & 31;
    if (lane >= 20) return;
    int m = (lane >= 10) ? 1 : 0;
    int q = lane - m * 10;
    const float4* in4 = (const float4*)(m == 0 ? in1 : in2);
    float4* out4      = (float4*)(m == 0 ? out1 : out2);
    int beg = g_off[r], end = g_off[r + 1];
    float d = g_dinv[r];
    float dd = d * d;
    float4 acc = in4[r * 10 + q];
    acc.x *= dd; acc.y *= dd; acc.z *= dd; acc.w *= dd;
    #pragma unroll 4
    for (int j = beg; j < end; j++) {
        int   c = __ldg(&g_ccol[j]);
        float w = __ldg(&g_cw[j]);
        float4 v = in4[c * 10 + q];
        acc.x += w * v.x;
        acc.y += w * v.y;
        acc.z += w * v.z;
        acc.w += w * v.w;
    }
    out4[r * 10 + q] = acc;
}

// ---------------- BatchNorm stats -------------------------------------------------
__global__ void k_bnzero() {
    int c = threadIdx.x;
    g_bnsum[c] = 0.f;
    g_bnsq[c]  = 0.f;
}

__global__ void k_bnstats(const float* __restrict__ h) {
    int c = threadIdx.x;
    float s = 0.f, s2 = 0.f;
    for (int r = blockIdx.x; r < NN; r += gridDim.x) {
        float v = h[r * HID + c];
        s += v;
        s2 += v * v;
    }
    atomicAdd(&g_bnsum[c], s);
    atomicAdd(&g_bnsq[c], s2);
}

__global__ void k_bnfin(const float* __restrict__ gamma, const float* __restrict__ beta) {
    int c = threadIdx.x;
    float mu  = g_bnsum[c] * (1.f / NN);
    float var = g_bnsq[c] * (1.f / NN) - mu * mu;
    float sc  = gamma[c] * rsqrtf(var + 1e-5f);
    g_scale[c] = sc;
    g_shift[c] = beta[c] - mu * sc;
}

// ---------------- host orchestration ----------------------------------------------
extern "C" void kernel_launch(void* const* d_in, const int* in_sizes, int n_in,
                              void* d_out, int out_size) {
    const float* x    = (const float*)d_in[0];
    const int*   ei   = (const int*)d_in[1];
    const int*   row  = ei;
    const int*   col  = ei + NE;
    const float* lab0 = (const float*)d_in[2];
    const float* lab1 = (const float*)d_in[3];
    const float* ew   = (const float*)d_in[4];
    const float* W0   = (const float*)d_in[5];
    const float* b0   = (const float*)d_in[6];
    const float* W1   = (const float*)d_in[7];
    const float* b1   = (const float*)d_in[8];
    const float* W2   = (const float*)d_in[9];
    const float* b2   = (const float*)d_in[10];
    const float* g0   = (const float*)d_in[11];
    const float* be0  = (const float*)d_in[12];
    const float* g1   = (const float*)d_in[13];
    const float* be1  = (const float*)d_in[14];
    float* out = (float*)d_out;

    float *bufA, *bufB, *t40, *y0, *y1, *y2, *y3, *degp;
    int* cntp;
    cudaGetSymbolAddress((void**)&bufA, g_bufA);
    cudaGetSymbolAddress((void**)&bufB, g_bufB);
    cudaGetSymbolAddress((void**)&t40,  g_t40);
    cudaGetSymbolAddress((void**)&y0,   g_y0);
    cudaGetSymbolAddress((void**)&y1,   g_y1);
    cudaGetSymbolAddress((void**)&y2,   g_y2);
    cudaGetSymbolAddress((void**)&y3,   g_y3);
    cudaGetSymbolAddress((void**)&degp, g_deg);
    cudaGetSymbolAddress((void**)&cntp, g_cnt);

    const int T = 256;
    const int gN   = (NN + T - 1) / T;
    const int gE   = (NE + T - 1) / T;
    const int gM64 = (NN + 63) / 64;
    const int gRW  = (NN + 7) / 8;

    // build prologue; gemm0 stays 4th (profiled launch)
    dim3 gg(NNP / 128, HID / 128);
    k_fillinit<<<gN, T>>>(degp, cntp, NN);
    k_degcnt<<<gE, T>>>(row, ew);
    k_dinv<<<gN, T>>>();
    k_gemm_tf32<<<gg, T>>>(x, W0, bufA, NN, HID, 512, 0);
    k_scan1<<<SB, 1024>>>();
    k_scan2<<<1, 1>>>();
    k_scan3<<<SB, 1024>>>();
    k_scatter<<<gE, T>>>(row, col, ew);

    // ---- layer 0 epilogue: spmm -> BN stats (apply fused into next gemm)
    k_gspmm256<<<NN / 4, T>>>(bufA, bufB, b0);
    k_bnzero<<<1, HID>>>();
    k_bnstats<<<512, HID>>>(bufB);
    k_bnfin<<<1, HID>>>(g0, be0);

    // ---- layer 1: gemm (BN0+ReLU fused in A-load) -> spmm -> BN stats
    k_gemm_tf32<<<gg, T>>>(bufB, W1, bufA, NN, HID, 256, 1);
    k_gspmm256<<<NN / 4, T>>>(bufA, bufB, b1);
    k_bnzero<<<1, HID>>>();
    k_bnstats<<<512, HID>>>(bufB);
    k_bnfin<<<1, HID>>>(g1, be1);

    // ---- layer 2 GEMM (BN1+ReLU fused in A-load) into t40
    k_gemm40<<<gM64, T>>>(bufB, W2, t40, NN, HID);

    // ---- fused 40-channel SpMMs (float4 lanes)
    float* dst1 = out + NN * OC;
    float* dst2 = out + 2 * NN * OC;
    k_gspmm40t<<<gRW, T>>>(t40, out, b2, lab0, y0, lab1, y2);
    k_gspmm40d<<<gRW, T>>>(y0, y1, y2, y3);
    k_gspmm40d<<<gRW, T>>>(y1, dst1, y3, dst2);
}

// round 14
// speedup vs baseline: 1.9270x; 1.0616x over previous
#include <cuda_runtime.h>
#include <mma.h>
using namespace nvcuda;

#define NN  50000
#define NNP 50048          // 391 * 128, padded row count for unguarded GEMM stores
#define NE  800000
#define HID 256
#define OC  40
#define SB  49             // scan blocks: 49*1024 >= NN

// ---------------- scratch (static device allocations) ---------------------------
__device__ float g_deg[NN];
__device__ float g_dinv[NN];
__device__ int   g_cnt[NN];
__device__ int   g_off[NN + 1];
__device__ int   g_cur[NN];
__device__ int   g_bsum[SB];
__device__ int   g_ccol[NE];
__device__ float g_cw[NE];
__device__ float g_bufA[NNP * HID];
__device__ float g_bufB[NNP * HID];
__device__ float g_t40[NN * OC];
__device__ float g_y0[NN * OC];
__device__ float g_y1[NN * OC];
__device__ float g_y2[NN * OC];
__device__ float g_y3[NN * OC];
__device__ float g_bnsum[HID];
__device__ float g_bnsq[HID];
__device__ float g_scale[HID];
__device__ float g_shift[HID];

// ---------------- normalization + CSR build --------------------------------------
__global__ void k_fillinit(float* degp, int* cntp, int n) {
    int i = blockIdx.x * blockDim.x + threadIdx.x;
    if (i < n) { degp[i] = 1.0f; cntp[i] = 0; }
}

__global__ void k_degcnt(const int* __restrict__ row, const float* __restrict__ w) {
    int e = blockIdx.x * blockDim.x + threadIdx.x;
    if (e < NE) {
        int r = row[e];
        atomicAdd(&g_deg[r], w[e]);
        atomicAdd(&g_cnt[r], 1);
    }
}

__global__ void k_dinv() {
    int i = blockIdx.x * blockDim.x + threadIdx.x;
    if (i < NN) {
        float d = g_deg[i];
        g_dinv[i] = (d > 0.f) ? rsqrtf(fmaxf(d, 1e-12f)) : 0.f;
    }
}

// phase 1: per-block exclusive scan (local), block totals to g_bsum
__global__ void k_scan1() {
    __shared__ int wsum[32];
    int tid = threadIdx.x, lane = tid & 31, wid = tid >> 5;
    int i = blockIdx.x * 1024 + tid;
    int v = (i < NN) ? g_cnt[i] : 0;
    int x = v;
    #pragma unroll
    for (int o = 1; o < 32; o <<= 1) {
        int t = __shfl_up_sync(0xFFFFFFFFu, x, o);
        if (lane >= o) x += t;
    }
    if (lane == 31) wsum[wid] = x;
    __syncthreads();
    if (wid == 0) {
        int s = wsum[lane];
        #pragma unroll
        for (int o = 1; o < 32; o <<= 1) {
            int t = __shfl_up_sync(0xFFFFFFFFu, s, o);
            if (lane >= o) s += t;
        }
        wsum[lane] = s;
    }
    __syncthreads();
    int warpoff = (wid > 0) ? wsum[wid - 1] : 0;
    if (i < NN) g_off[i] = warpoff + x - v;            // local exclusive
    if (tid == 1023) g_bsum[blockIdx.x] = warpoff + x;  // block total
}

// phase 2: serial scan of SB block sums (tiny)
__global__ void k_scan2() {
    int acc = 0;
    for (int b = 0; b < SB; b++) {
        int t = g_bsum[b];
        g_bsum[b] = acc;
        acc += t;
    }
    g_off[NN] = acc;
}

// phase 3: add block offsets, copy to g_cur
__global__ void k_scan3() {
    int i = blockIdx.x * 1024 + threadIdx.x;
    if (i < NN) {
        int v = g_off[i] + g_bsum[blockIdx.x];
        g_off[i] = v;
        g_cur[i] = v;
    }
}

__global__ void k_scatter(const int* __restrict__ row, const int* __restrict__ col,
                          const float* __restrict__ w) {
    int e = blockIdx.x * blockDim.x + threadIdx.x;
    if (e < NE) {
        int r = row[e], c = col[e];
        int p = atomicAdd(&g_cur[r], 1);
        g_ccol[p] = c;
        g_cw[p] = g_dinv[r] * w[e] * g_dinv[c];
    }
}

// ---------------- TF32 tensor-core GEMM: C[M,N] = op(A)[M,K] @ B[K,N] ------------
// block tile 128x128, 8 warps (4 m x 2 n), warp tile 32x64, k chunk 32.
// bn != 0: A element (channel = k index) transformed relu(a*scale[k]+shift[k]).
__global__ void __launch_bounds__(256) k_gemm_tf32(const float* __restrict__ A,
                                                   const float* __restrict__ B,
                                                   float* __restrict__ C,
                                                   int M, int N, int K, int bn) {
    __shared__ float As[128][40];    // [m][k], k chunk 32
    __shared__ float Bs[32][136];    // [k][n], n chunk 128
    int bm = blockIdx.x * 128, bnn = blockIdx.y * 128;
    int tid = threadIdx.x;
    int warp = tid >> 5;
    int wm = (warp >> 1) * 32;       // 4 warps along m
    int wn = (warp & 1) * 64;        // 2 warps along n

    wmma::fragment<wmma::accumulator, 16, 16, 8, float> c[2][4];
    #pragma unroll
    for (int i = 0; i < 2; i++)
        #pragma unroll
        for (int j = 0; j < 4; j++)
            wmma::fill_fragment(c[i][j], 0.f);

    for (int k0 = 0; k0 < K; k0 += 32) {
        {
            int m  = tid >> 1;
            int ks = (tid & 1) * 16;
            int gr = bm + m;
            if (gr < M) {
                const float4* p = (const float4*)&A[(long long)gr * K + k0 + ks];
                #pragma unroll
                for (int i = 0; i < 4; i++) {
                    float4 v = p[i];
                    if (bn) {
                        int cc = k0 + ks + i * 4;
                        v.x = fmaxf(v.x * g_scale[cc + 0] + g_shift[cc + 0], 0.f);
                        v.y = fmaxf(v.y * g_scale[cc + 1] + g_shift[cc + 1], 0.f);
                        v.z = fmaxf(v.z * g_scale[cc + 2] + g_shift[cc + 2], 0.f);
                        v.w = fmaxf(v.w * g_scale[cc + 3] + g_shift[cc + 3], 0.f);
                    }
                    As[m][ks + i * 4 + 0] = wmma::__float_to_tf32(v.x);
                    As[m][ks + i * 4 + 1] = wmma::__float_to_tf32(v.y);
                    As[m][ks + i * 4 + 2] = wmma::__float_to_tf32(v.z);
                    As[m][ks + i * 4 + 3] = wmma::__float_to_tf32(v.w);
                }
            } else {
                #pragma unroll
                for (int i = 0; i < 16; i++) As[m][ks + i] = 0.f;
            }
        }
        {
            int k   = tid >> 3;
            int n16 = (tid & 7) * 16;
            const float4* p = (const float4*)&B[(long long)(k0 + k) * N + bnn + n16];
            #pragma unroll
            for (int i = 0; i < 4; i++) {
                float4 v = p[i];
                Bs[k][n16 + i * 4 + 0] = wmma::__float_to_tf32(v.x);
                Bs[k][n16 + i * 4 + 1] = wmma::__float_to_tf32(v.y);
                Bs[k][n16 + i * 4 + 2] = wmma::__float_to_tf32(v.z);
                Bs[k][n16 + i * 4 + 3] = wmma::__float_to_tf32(v.w);
            }
        }
        __syncthreads();
        #pragma unroll
        for (int kk = 0; kk < 32; kk += 8) {
            wmma::fragment<wmma::matrix_a, 16, 16, 8, wmma::precision::tf32, wmma::row_major> a0, a1;
            wmma::fragment<wmma::matrix_b, 16, 16, 8, wmma::precision::tf32, wmma::row_major> b[4];
            wmma::load_matrix_sync(a0, &As[wm +  0][kk], 40);
            wmma::load_matrix_sync(a1, &As[wm + 16][kk], 40);
            #pragma unroll
            for (int j = 0; j < 4; j++)
                wmma::load_matrix_sync(b[j], &Bs[kk][wn + 16 * j], 136);
            #pragma unroll
            for (int j = 0; j < 4; j++) {
                wmma::mma_sync(c[0][j], a0, b[j], c[0][j]);
                wmma::mma_sync(c[1][j], a1, b[j], c[1][j]);
            }
        }
        __syncthreads();
    }
    #pragma unroll
    for (int i = 0; i < 2; i++)
        #pragma unroll
        for (int j = 0; j < 4; j++)
            wmma::store_matrix_sync(
                &C[(long long)(bm + wm + 16 * i) * N + bnn + wn + 16 * j],
                c[i][j], N, wmma::mem_row_major);
}

// ---------------- GEMM: C[M,40] = relu(bn(A))[M,K] @ B[K,40] (SIMT) --------------
__global__ void k_gemm40(const float* __restrict__ A, const float* __restrict__ B,
                         float* __restrict__ C, int M, int K) {
    __shared__ float As[64][33];
    __shared__ float Bs[32][40];
    int bm = blockIdx.x * 64;
    int r  = threadIdx.x >> 2;
    int cg = threadIdx.x & 3;
    float acc[10] = {};
    for (int k0 = 0; k0 < K; k0 += 32) {
        int kk = (threadIdx.x & 3) * 8;
        int gr = bm + r;
        #pragma unroll
        for (int i = 0; i < 8; i++) {
            int c = k0 + kk + i;
            float v = (gr < M) ? A[(long long)gr * K + c] : 0.f;
            As[r][kk + i] = fmaxf(v * g_scale[c] + g_shift[c], 0.f);
        }
        for (int i = threadIdx.x; i < 32 * 40; i += 256) {
            int k = i / 40, n = i % 40;
            Bs[k][n] = B[(k0 + k) * 40 + n];
        }
        __syncthreads();
        #pragma unroll
        for (int k = 0; k < 32; k++) {
            float a = As[r][k];
            #pragma unroll
            for (int j = 0; j < 10; j++) acc[j] += a * Bs[k][cg + j * 4];
        }
        __syncthreads();
    }
    int gr = bm + r;
    if (gr < M)
        #pragma unroll
        for (int j = 0; j < 10; j++) C[gr * 40 + cg + j * 4] = acc[j];
}

// ---------------- gather SpMM 256ch (float4, no smem, no barriers) ---------------
__global__ void __launch_bounds__(256) k_gspmm256(const float* __restrict__ in,
                                                  float* __restrict__ out,
                                                  const float* __restrict__ bias) {
    int r    = blockIdx.x * 4 + (threadIdx.x >> 6);   // NN divisible by 4
    int lane = threadIdx.x & 63;                      // channel group (4 ch)
    int beg = g_off[r], end = g_off[r + 1];
    float d = g_dinv[r];
    float dd = d * d;
    const float4* in4 = (const float4*)in;
    float4 acc = in4[r * 64 + lane];
    float4 bv  = ((const float4*)bias)[lane];
    acc.x = dd * acc.x + bv.x;
    acc.y = dd * acc.y + bv.y;
    acc.z = dd * acc.z + bv.z;
    acc.w = dd * acc.w + bv.w;
    #pragma unroll 2
    for (int j = beg; j < end; j++) {
        int   c = __ldg(&g_ccol[j]);
        float w = __ldg(&g_cw[j]);
        float4 v = in4[c * 64 + lane];
        acc.x += w * v.x;
        acc.y += w * v.y;
        acc.z += w * v.z;
        acc.w += w * v.w;
    }
    ((float4*)out)[r * 64 + lane] = acc;
}

// ---------------- 40-channel gather SpMM, float4 lanes ---------------------------
// dual: warp per row; lane = matrix * 10 + quad (20 active lanes).
__global__ void __launch_bounds__(256) k_gspmm40d(
    const float* __restrict__ in1, float* __restrict__ out1,
    const float* __restrict__ in2, float* __restrict__ out2) {
    int r = blockIdx.x * 8 + (threadIdx.x >> 5);
    if (r >= NN) return;
    int lane = threadIdx.x & 31;
    if (lane >= 20) return;
    int m = (lane >= 10) ? 1 : 0;
    int q = lane - m * 10;
    const float4* in4 = (const float4*)(m == 0 ? in1 : in2);
    float4* out4      = (float4*)(m == 0 ? out1 : out2);
    int beg = g_off[r], end = g_off[r + 1];
    float d = g_dinv[r];
    float dd = d * d;
    float4 acc = in4[r * 10 + q];
    acc.x *= dd; acc.y *= dd; acc.z *= dd; acc.w *= dd;
    #pragma unroll 4
    for (int j = beg; j < end; j++) {
        int   c = __ldg(&g_ccol[j]);
        float w = __ldg(&g_cw[j]);
        float4 v = in4[c * 10 + q];
        acc.x += w * v.x;
        acc.y += w * v.y;
        acc.z += w * v.z;
        acc.w += w * v.w;
    }
    out4[r * 10 + q] = acc;
}

// single + bias: warp per row, 10 active lanes (feature output pass).
__global__ void __launch_bounds__(256) k_gspmm40s(
    const float* __restrict__ in, float* __restrict__ out,
    const float* __restrict__ bias) {
    int r = blockIdx.x * 8 + (threadIdx.x >> 5);
    if (r >= NN) return;
    int q = threadIdx.x & 31;
    if (q >= 10) return;
    const float4* in4 = (const float4*)in;
    int beg = g_off[r], end = g_off[r + 1];
    float d = g_dinv[r];
    float dd = d * d;
    float4 acc = in4[r * 10 + q];
    float4 bv  = ((const float4*)bias)[q];
    acc.x = dd * acc.x + bv.x;
    acc.y = dd * acc.y + bv.y;
    acc.z = dd * acc.z + bv.z;
    acc.w = dd * acc.w + bv.w;
    #pragma unroll 4
    for (int j = beg; j < end; j++) {
        int   c = __ldg(&g_ccol[j]);
        float w = __ldg(&g_cw[j]);
        float4 v = in4[c * 10 + q];
        acc.x += w * v.x;
        acc.y += w * v.y;
        acc.z += w * v.z;
        acc.w += w * v.w;
    }
    ((float4*)out)[r * 10 + q] = acc;
}

// ---------------- BatchNorm stats -------------------------------------------------
__global__ void k_bnzero() {
    int c = threadIdx.x;
    g_bnsum[c] = 0.f;
    g_bnsq[c]  = 0.f;
}

__global__ void k_bnstats(const float* __restrict__ h) {
    int c = threadIdx.x;
    float s = 0.f, s2 = 0.f;
    for (int r = blockIdx.x; r < NN; r += gridDim.x) {
        float v = h[r * HID + c];
        s += v;
        s2 += v * v;
    }
    atomicAdd(&g_bnsum[c], s);
    atomicAdd(&g_bnsq[c], s2);
}

__global__ void k_bnfin(const float* __restrict__ gamma, const float* __restrict__ beta) {
    int c = threadIdx.x;
    float mu  = g_bnsum[c] * (1.f / NN);
    float var = g_bnsq[c] * (1.f / NN) - mu * mu;
    float sc  = gamma[c] * rsqrtf(var + 1e-5f);
    g_scale[c] = sc;
    g_shift[c] = beta[c] - mu * sc;
}

// ---------------- host orchestration ----------------------------------------------
extern "C" void kernel_launch(void* const* d_in, const int* in_sizes, int n_in,
                              void* d_out, int out_size) {
    const float* x    = (const float*)d_in[0];
    const int*   ei   = (const int*)d_in[1];
    const int*   row  = ei;
    const int*   col  = ei + NE;
    const float* lab0 = (const float*)d_in[2];
    const float* lab1 = (const float*)d_in[3];
    const float* ew   = (const float*)d_in[4];
    const float* W0   = (const float*)d_in[5];
    const float* b0   = (const float*)d_in[6];
    const float* W1   = (const float*)d_in[7];
    const float* b1   = (const float*)d_in[8];
    const float* W2   = (const float*)d_in[9];
    const float* b2   = (const float*)d_in[10];
    const float* g0   = (const float*)d_in[11];
    const float* be0  = (const float*)d_in[12];
    const float* g1   = (const float*)d_in[13];
    const float* be1  = (const float*)d_in[14];
    float* out = (float*)d_out;

    float *bufA, *bufB, *t40, *y0, *y1, *y2, *y3, *degp;
    int* cntp;
    cudaGetSymbolAddress((void**)&bufA, g_bufA);
    cudaGetSymbolAddress((void**)&bufB, g_bufB);
    cudaGetSymbolAddress((void**)&t40,  g_t40);
    cudaGetSymbolAddress((void**)&y0,   g_y0);
    cudaGetSymbolAddress((void**)&y1,   g_y1);
    cudaGetSymbolAddress((void**)&y2,   g_y2);
    cudaGetSymbolAddress((void**)&y3,   g_y3);
    cudaGetSymbolAddress((void**)&degp, g_deg);
    cudaGetSymbolAddress((void**)&cntp, g_cnt);

    const int T = 256;
    const int gN   = (NN + T - 1) / T;
    const int gE   = (NE + T - 1) / T;
    const int gM64 = (NN + 63) / 64;
    const int gRW  = (NN + 7) / 8;
    dim3 gg(NNP / 128, HID / 128);
    float* dst1 = out + NN * OC;
    float* dst2 = out + 2 * NN * OC;

    // one-time creation of stream/event handles (reused on every call so the
    // capture call performs no new allocations; work per call is identical).
    static cudaStream_t s1 = nullptr, s2 = nullptr;
    static cudaEvent_t evRoot = nullptr, evG0 = nullptr, evCsr = nullptr, evLp = nullptr;
    if (s1 == nullptr) {
        cudaStreamCreateWithFlags(&s1, cudaStreamNonBlocking);
        cudaStreamCreateWithFlags(&s2, cudaStreamNonBlocking);
        cudaEventCreateWithFlags(&evRoot, cudaEventDisableTiming);
        cudaEventCreateWithFlags(&evG0,  cudaEventDisableTiming);
        cudaEventCreateWithFlags(&evCsr, cudaEventDisableTiming);
        cudaEventCreateWithFlags(&evLp,  cudaEventDisableTiming);
    }

    // fork: gemm0 on s1 (independent of CSR build)
    cudaEventRecord(evRoot, 0);
    cudaStreamWaitEvent(s1, evRoot, 0);
    k_gemm_tf32<<<gg, T, 0, s1>>>(x, W0, bufA, NN, HID, 512, 0);
    cudaEventRecord(evG0, s1);

    // CSR build on default stream (concurrent with gemm0)
    k_fillinit<<<gN, T>>>(degp, cntp, NN);
    k_degcnt<<<gE, T>>>(row, ew);
    k_dinv<<<gN, T>>>();
    k_scan1<<<SB, 1024>>>();
    k_scan2<<<1, 1>>>();
    k_scan3<<<SB, 1024>>>();
    k_scatter<<<gE, T>>>(row, col, ew);
    cudaEventRecord(evCsr, 0);

    // fork: label-prop chain on s2 (needs only CSR); runs under feature path
    cudaStreamWaitEvent(s2, evCsr, 0);
    k_gspmm40d<<<gRW, T, 0, s2>>>(lab0, y0, lab1, y2);
    k_gspmm40d<<<gRW, T, 0, s2>>>(y0, y1, y2, y3);
    k_gspmm40d<<<gRW, T, 0, s2>>>(y1, dst1, y3, dst2);
    cudaEventRecord(evLp, s2);

    // feature path (default stream) waits for gemm0
    cudaStreamWaitEvent(0, evG0, 0);
    k_gspmm256<<<NN / 4, T>>>(bufA, bufB, b0);
    k_bnzero<<<1, HID>>>();
    k_bnstats<<<512, HID>>>(bufB);
    k_bnfin<<<1, HID>>>(g0, be0);

    k_gemm_tf32<<<gg, T>>>(bufB, W1, bufA, NN, HID, 256, 1);
    k_gspmm256<<<NN / 4, T>>>(bufA, bufB, b1);
    k_bnzero<<<1, HID>>>();
    k_bnstats<<<512, HID>>>(bufB);
    k_bnfin<<<1, HID>>>(g1, be1);

    k_gemm40<<<gM64, T>>>(bufB, W2, t40, NN, HID);
    k_gspmm40s<<<gRW, T>>>(t40, out, b2);

    // join label-prop branch
    cudaStreamWaitEvent(0, evLp, 0);
}